// round 1
// baseline (speedup 1.0000x reference)
#include <cuda_runtime.h>
#include <math.h>

// Problem constants
#define BATCH 8
#define SEQ   4096
#define DIM   3
#define PP    400          // 20x20
#define NSAMP (BATCH*SEQ)  // 32768

// ---------------- scratch (static __device__, no allocations) ----------------
__device__ float g_h1[NSAMP * PP];     // ln1 output, (sample, q)  52 MB
__device__ float g_m[NSAMP];           // mean over D of x0
__device__ float g_wT[PP * PP];        // fc2_w transposed: [k][q]
__device__ float g_keff[25];           // composed 5x5 circular kernel
__device__ float g_c;                  // composed bias (after channel mean)
__device__ float g_act0[BATCH * PP];   // iteration-0 activities
__device__ int   g_mask[BATCH * PP];   // selection mask

// ---------------- prep: transpose fc2_w, compose conv1*conv2 ----------------
__global__ void prep_kernel(const float* __restrict__ fc2_w,
                            const float* __restrict__ c1w, const float* __restrict__ c1b,
                            const float* __restrict__ c2w, const float* __restrict__ c2b)
{
    int idx = blockIdx.x * 256 + threadIdx.x;
    if (idx < PP * PP) {
        int q = idx / PP, k = idx % PP;
        g_wT[k * PP + q] = fc2_w[idx];
    }
    if (blockIdx.x == 0 && threadIdx.x < 26) {
        int t = threadIdx.x;
        if (t < 25) {
            // K5[u][v] = (1/10) sum_{oc,ic} sum_{ay+by=u, ax+bx=v} w2[oc,ic,by,bx]*w1[ic,ay,ax]
            int u = t / 5, v = t % 5;
            float acc = 0.f;
            for (int oc = 0; oc < 10; ++oc)
                for (int ic = 0; ic < 5; ++ic)
                    for (int ay = 0; ay < 3; ++ay) {
                        int by = u - ay; if (by < 0 || by > 2) continue;
                        for (int ax = 0; ax < 3; ++ax) {
                            int bx = v - ax; if (bx < 0 || bx > 2) continue;
                            acc += c2w[((oc * 5 + ic) * 3 + by) * 3 + bx]
                                 * c1w[(ic * 3 + ay) * 3 + ax];
                        }
                    }
            g_keff[t] = acc * 0.1f;
        } else {
            // c = (1/10) sum_oc [ b2[oc] + sum_ic b1[ic]*sum_b w2[oc,ic,b] ]
            float acc = 0.f;
            for (int oc = 0; oc < 10; ++oc) {
                float t2 = c2b[oc];
                for (int ic = 0; ic < 5; ++ic) {
                    float sw = 0.f;
                    for (int bb = 0; bb < 9; ++bb) sw += c2w[(oc * 5 + ic) * 9 + bb];
                    t2 += c1b[ic] * sw;
                }
                acc += t2;
            }
            g_c = acc * 0.1f;
        }
    }
}

// ---------------- kernel A: fc1 + relu + ln1, and m = mean(x0) ---------------
__global__ void __launch_bounds__(256) kernelA(const float* __restrict__ x0,
    const float* __restrict__ fc1_w, const float* __restrict__ fc1_b,
    const float* __restrict__ ln1_g, const float* __restrict__ ln1_b)
{
    __shared__ float fw[PP * 3], fb[PP], lg[PP], lb[PP];
    int tid = threadIdx.x;
    for (int i = tid; i < PP * 3; i += 256) fw[i] = fc1_w[i];
    for (int i = tid; i < PP; i += 256) { fb[i] = fc1_b[i]; lg[i] = ln1_g[i]; lb[i] = ln1_b[i]; }
    __syncthreads();

    int lane = tid & 31, wid = tid >> 5;
    int ss = blockIdx.x * 8 + wid;          // one warp per sample
    const float* xp = x0 + (size_t)ss * 3;
    float xa = xp[0], xb = xp[1], xc = xp[2];
    if (lane == 0) g_m[ss] = (xa + xb + xc) * (1.f / 3.f);

    float v[13];
    float sum = 0.f, sq = 0.f;
#pragma unroll
    for (int k = 0; k < 13; ++k) {
        int q = lane + 32 * k;
        float h = 0.f;
        if (q < PP) {
            h = xa * fw[q * 3] + xb * fw[q * 3 + 1] + xc * fw[q * 3 + 2] + fb[q];
            h = fmaxf(h, 0.f);
        }
        v[k] = h; sum += h; sq += h * h;
    }
    for (int o = 16; o; o >>= 1) {
        sum += __shfl_xor_sync(~0u, sum, o);
        sq  += __shfl_xor_sync(~0u, sq, o);
    }
    float mu = sum * (1.f / PP);
    float var = sq * (1.f / PP) - mu * mu;
    float rs = rsqrtf(var + 1e-5f);
    float* hp = g_h1 + (size_t)ss * PP;
#pragma unroll
    for (int k = 0; k < 13; ++k) {
        int q = lane + 32 * k;
        if (q < PP) hp[q] = (v[k] - mu) * rs * lg[q] + lb[q];
    }
}

// ---------------- kernel B: fc2 GEMM + relu + ln2 + conv5x5 + sigmoid --------
// block = 64 samples x all 400 outputs; 256 threads; TM=4, TN=25, BK=16
#define BM 64
#define BK 16
#define SM_AS (BM * 20)        // [m][k] pad 20
#define SM_BS (BK * 404)       // [k][q] pad 404
#define SM_CS (BM * 401)       // [m][q] pad 401
__global__ void __launch_bounds__(256, 1) kernelB(
    const float* __restrict__ fc2_b, const float* __restrict__ ln2_g,
    const float* __restrict__ ln2_b, float* __restrict__ out)
{
    extern __shared__ float sm[];
    float* As  = sm;
    float* Bs  = As + SM_AS;
    float* Cs  = Bs + SM_BS;
    float* pb  = Cs + SM_CS;      // fc2_b [400]
    float* pg  = pb + PP;         // ln2_g
    float* pb2 = pg + PP;         // ln2_b
    float* ks  = pb2 + PP;        // keff[25] + c

    int tid = threadIdx.x;
    int s0 = blockIdx.x * BM;

    for (int q = tid; q < PP; q += 256) { pb[q] = fc2_b[q]; pg[q] = ln2_g[q]; pb2[q] = ln2_b[q]; }
    if (tid < 26) ks[tid] = (tid < 25) ? g_keff[tid] : g_c;

    int tr = tid >> 4, tc = tid & 15;
    float acc[4][25];
#pragma unroll
    for (int i = 0; i < 4; ++i)
#pragma unroll
        for (int j = 0; j < 25; ++j) acc[i][j] = 0.f;

    for (int kk = 0; kk < PP; kk += BK) {
        __syncthreads();
        {   // load As: 64 rows x 16 k, 256 float4
            int mrow = tid >> 2, k4 = (tid & 3) * 4;
            float4 v = *(const float4*)(g_h1 + (size_t)(s0 + mrow) * PP + kk + k4);
            *(float4*)(As + mrow * 20 + k4) = v;
        }
        for (int f = tid; f < 1600; f += 256) {   // Bs: 16 x 400, 1600 float4
            int krow = f / 100, q4 = (f % 100) * 4;
            float4 v = *(const float4*)(g_wT + (kk + krow) * PP + q4);
            *(float4*)(Bs + krow * 404 + q4) = v;
        }
        __syncthreads();
#pragma unroll
        for (int k = 0; k < BK; ++k) {
            float a[4], bq[25];
#pragma unroll
            for (int i = 0; i < 4; ++i) a[i] = As[(tr * 4 + i) * 20 + k];
#pragma unroll
            for (int j = 0; j < 25; ++j) bq[j] = Bs[k * 404 + tc * 25 + j];
#pragma unroll
            for (int i = 0; i < 4; ++i)
#pragma unroll
                for (int j = 0; j < 25; ++j) acc[i][j] += a[i] * bq[j];
        }
    }
    __syncthreads();

    // bias + relu -> Cs
#pragma unroll
    for (int i = 0; i < 4; ++i)
#pragma unroll
        for (int j = 0; j < 25; ++j) {
            int q = tc * 25 + j;
            Cs[(tr * 4 + i) * 401 + q] = fmaxf(acc[i][j] + pb[q], 0.f);
        }
    __syncthreads();

    // LN2 per sample row (8 warps x 8 rows)
    int lane = tid & 31, wid = tid >> 5;
    for (int r = wid * 8; r < wid * 8 + 8; ++r) {
        float sum = 0.f, sq = 0.f;
#pragma unroll
        for (int k = 0; k < 13; ++k) {
            int q = lane + 32 * k;
            if (q < PP) { float x = Cs[r * 401 + q]; sum += x; sq += x * x; }
        }
        for (int o = 16; o; o >>= 1) {
            sum += __shfl_xor_sync(~0u, sum, o);
            sq  += __shfl_xor_sync(~0u, sq, o);
        }
        float mu = sum * (1.f / PP);
        float var = sq * (1.f / PP) - mu * mu;
        float rs = rsqrtf(var + 1e-5f);
#pragma unroll
        for (int k = 0; k < 13; ++k) {
            int q = lane + 32 * k;
            if (q < PP) {
                float x = Cs[r * 401 + q];
                Cs[r * 401 + q] = (x - mu) * rs * pg[q] + pb2[q];
            }
        }
    }
    __syncthreads();

    // 5x5 circular conv + sigmoid + transposed write
    int b = s0 >> 12;          // SEQ=4096
    int sw = s0 & (SEQ - 1);
    float kreg[25];
#pragma unroll
    for (int d = 0; d < 25; ++d) kreg[d] = ks[d];
    float cc = ks[25];

    for (int pi = 0; pi < 2; ++pi) {
        int p = tid + pi * 256;
        if (p < PP) {
            int ii = p / 20, jj = p % 20;
            int nb[25];
#pragma unroll
            for (int d = 0; d < 25; ++d) {
                int du = d / 5 - 2, dv = d % 5 - 2;
                int y = (ii + du + 20) % 20;
                int x = (jj + dv + 20) % 20;
                nb[d] = y * 20 + x;
            }
            float* obase = out + ((size_t)(b * PP + p)) * SEQ + sw;
            for (int r8 = 0; r8 < BM; r8 += 8) {
                float o8[8];
#pragma unroll
                for (int rr = 0; rr < 8; ++rr) o8[rr] = cc;
#pragma unroll
                for (int d = 0; d < 25; ++d) {
                    float kv = kreg[d];
#pragma unroll
                    for (int rr = 0; rr < 8; ++rr)
                        o8[rr] += kv * Cs[(r8 + rr) * 401 + nb[d]];
                }
#pragma unroll
                for (int rr = 0; rr < 8; ++rr) o8[rr] = 1.f / (1.f + __expf(-o8[rr]));
                *(float4*)(obase + r8)     = make_float4(o8[0], o8[1], o8[2], o8[3]);
                *(float4*)(obase + r8 + 4) = make_float4(o8[4], o8[5], o8[6], o8[7]);
            }
        }
    }
}

// ---------------- act0: iteration-0 activities (res = 1) --------------------
__global__ void act0_kernel(const float* __restrict__ w)
{
    int gw = blockIdx.x * 8 + (threadIdx.x >> 5);
    int lane = threadIdx.x & 31;
    int b = gw / PP, p = gw % PP;
    const float4* wp = (const float4*)(w + ((size_t)(b * PP + p)) * SEQ);
    const float4* mp = (const float4*)(g_m + (size_t)b * SEQ);
    float a = 0.f;
    for (int k = lane; k < SEQ / 4; k += 32) {
        float4 x = wp[k]; float4 mm = mp[k];
        a += x.x * x.x * mm.x * mm.x + x.y * x.y * mm.y * mm.y
           + x.z * x.z * mm.z * mm.z + x.w * x.w * mm.w * mm.w;
    }
    for (int o = 16; o; o >>= 1) a += __shfl_xor_sync(~0u, a, o);
    if (lane == 0) g_act0[gw] = a;
}

// ---------------- selection: one block per batch, early exit ----------------
__global__ void __launch_bounds__(1024) select_kernel(const float* __restrict__ w)
{
    int b = blockIdx.x;
    extern __shared__ float dyn[];
    float* res = dyn;            // 4096
    float* v2  = dyn + SEQ;      // 4096
    float* msh = dyn + 2 * SEQ;  // 4096
    __shared__ float acts[PP];
    __shared__ int   sel[PP];
    __shared__ float wvv[32];
    __shared__ int   wii[32];
    __shared__ float rsum[32];
    __shared__ int   s_pid, s_done;

    int tid = threadIdx.x, lane = tid & 31, wid = tid >> 5;
    for (int s = tid; s < SEQ; s += 1024) { res[s] = 1.f; msh[s] = g_m[(size_t)b * SEQ + s]; }
    for (int p = tid; p < PP; p += 1024) sel[p] = 0;
    __syncthreads();

    const float* wb = w + (size_t)b * PP * SEQ;

    for (int it = 0; it < PP; ++it) {
        // activities
        if (it == 0) {
            for (int p = tid; p < PP; p += 1024) acts[p] = g_act0[b * PP + p];
        } else {
            for (int p = wid; p < PP; p += 32) {
                float a = 0.f;
                if (!sel[p]) {
                    const float4* wp = (const float4*)(wb + (size_t)p * SEQ);
                    const float4* vv = (const float4*)v2;
#pragma unroll 4
                    for (int k = lane; k < SEQ / 4; k += 32) {
                        float4 x = wp[k]; float4 y = vv[k];
                        a += x.x * x.x * y.x + x.y * x.y * y.y
                           + x.z * x.z * y.z + x.w * x.w * y.w;
                    }
                    for (int o = 16; o; o >>= 1) a += __shfl_xor_sync(~0u, a, o);
                }
                if (lane == 0) acts[p] = sel[p] ? 0.f : a;
            }
        }
        __syncthreads();

        // argmax, ties -> lowest index (matches jnp.argmax)
        float bv = -1.f; int bi = 0x7fffffff;
        for (int p = tid; p < PP; p += 1024) {
            float v = acts[p];
            if (v > bv || (v == bv && p < bi)) { bv = v; bi = p; }
        }
        for (int o = 16; o; o >>= 1) {
            float ov = __shfl_xor_sync(~0u, bv, o);
            int   oi = __shfl_xor_sync(~0u, bi, o);
            if (ov > bv || (ov == bv && oi < bi)) { bv = ov; bi = oi; }
        }
        if (lane == 0) { wvv[wid] = bv; wii[wid] = bi; }
        __syncthreads();
        if (tid == 0) {
            float fv = -1.f; int fi = 0x7fffffff;
            for (int i = 0; i < 32; ++i)
                if (wvv[i] > fv || (wvv[i] == fv && wii[i] < fi)) { fv = wvv[i]; fi = wii[i]; }
            s_pid = fi; sel[fi] = 1;
        }
        __syncthreads();
        int pid = s_pid;

        // res update + mean
        const float* row = wb + (size_t)pid * SEQ;
        float loc = 0.f;
        for (int s = tid; s < SEQ; s += 1024) {
            float r = res[s] - row[s];
            r = r > 0.f ? r : 0.f;
            res[s] = r; loc += r;
        }
        for (int o = 16; o; o >>= 1) loc += __shfl_xor_sync(~0u, loc, o);
        if (lane == 0) rsum[wid] = loc;
        __syncthreads();
        if (tid == 0) {
            float t = 0.f;
            for (int i = 0; i < 32; ++i) t += rsum[i];
            s_done = (t * (1.f / SEQ) < 0.05f) ? 1 : 0;
        }
        __syncthreads();
        if (s_done) break;

        for (int s = tid; s < SEQ; s += 1024) { float v = res[s] * msh[s]; v2[s] = v * v; }
        __syncthreads();
    }

    for (int p = tid; p < PP; p += 1024) g_mask[b * PP + p] = sel[p];
}

// ---------------- final scale: out *= mask ? 1 : 0.1 ------------------------
__global__ void scale_kernel(float* __restrict__ out)
{
    int idx = blockIdx.x * 256 + threadIdx.x;   // float4 index
    float4* o4 = (float4*)out;
    int bp = idx >> 10;                          // 4096/4 float4 per row
    float sc = g_mask[bp] ? 1.f : 0.1f;
    float4 v = o4[idx];
    v.x *= sc; v.y *= sc; v.z *= sc; v.w *= sc;
    o4[idx] = v;
}

// ---------------- launch --------------------------------------------------
extern "C" void kernel_launch(void* const* d_in, const int* in_sizes, int n_in,
                              void* d_out, int out_size)
{
    const float* x0     = (const float*)d_in[0];
    const float* fc1_w  = (const float*)d_in[1];
    const float* fc1_b  = (const float*)d_in[2];
    const float* ln1_g  = (const float*)d_in[3];
    const float* ln1_b  = (const float*)d_in[4];
    const float* fc2_w  = (const float*)d_in[5];
    const float* fc2_b  = (const float*)d_in[6];
    const float* ln2_g  = (const float*)d_in[7];
    const float* ln2_b  = (const float*)d_in[8];
    const float* c1w    = (const float*)d_in[9];
    const float* c1b    = (const float*)d_in[10];
    const float* c2w    = (const float*)d_in[11];
    const float* c2b    = (const float*)d_in[12];
    float* out = (float*)d_out;

    const int smemB = (SM_AS + SM_BS + SM_CS + 3 * PP + 26) * sizeof(float);
    cudaFuncSetAttribute(kernelB, cudaFuncAttributeMaxDynamicSharedMemorySize, smemB);
    cudaFuncSetAttribute(select_kernel, cudaFuncAttributeMaxDynamicSharedMemorySize,
                         3 * SEQ * (int)sizeof(float));

    prep_kernel<<<625, 256>>>(fc2_w, c1w, c1b, c2w, c2b);
    kernelA<<<NSAMP / 8, 256>>>(x0, fc1_w, fc1_b, ln1_g, ln1_b);
    kernelB<<<NSAMP / BM, 256, smemB>>>(fc2_b, ln2_g, ln2_b, out);
    act0_kernel<<<BATCH * PP / 8, 256>>>(out);
    select_kernel<<<BATCH, 1024, 3 * SEQ * sizeof(float)>>>(out);
    scale_kernel<<<(NSAMP * PP / 4) / 256, 256>>>(out);
}

// round 2
// speedup vs baseline: 1.0942x; 1.0942x over previous
#include <cuda_runtime.h>
#include <math.h>

// Problem constants
#define BATCH 8
#define SEQ   4096
#define DIM   3
#define PP    400          // 20x20
#define NSAMP (BATCH*SEQ)  // 32768
#define ITERS 12           // fixed selection iteration count (early-exit via flags)

// ---------------- scratch (static __device__, no allocations) ----------------
__device__ float g_h1[NSAMP * PP];     // ln1 output, (sample, q)  52 MB
__device__ float g_m[NSAMP];           // mean over D of x0
__device__ float g_wT[PP * PP];        // fc2_w transposed: [k][q]
__device__ float g_keff[25];           // composed 5x5 circular kernel
__device__ float g_c;                  // composed bias (after channel mean)
__device__ float g_act[BATCH * PP];    // per-iteration activities
__device__ int   g_sel[BATCH * PP];    // selection mask
__device__ int   g_done[BATCH];        // per-batch early-exit flag
__device__ float g_res[BATCH * SEQ];   // residual
__device__ float g_v2[BATCH * SEQ];    // (res*m)^2

// ---------------- prep: transpose fc2_w, compose conv1*conv2 ----------------
__global__ void prep_kernel(const float* __restrict__ fc2_w,
                            const float* __restrict__ c1w, const float* __restrict__ c1b,
                            const float* __restrict__ c2w, const float* __restrict__ c2b)
{
    int idx = blockIdx.x * 256 + threadIdx.x;
    if (idx < PP * PP) {
        int q = idx / PP, k = idx % PP;
        g_wT[k * PP + q] = fc2_w[idx];
    }
    if (blockIdx.x == 0 && threadIdx.x < 26) {
        int t = threadIdx.x;
        if (t < 25) {
            int u = t / 5, v = t % 5;
            float acc = 0.f;
            for (int oc = 0; oc < 10; ++oc)
                for (int ic = 0; ic < 5; ++ic)
                    for (int ay = 0; ay < 3; ++ay) {
                        int by = u - ay; if (by < 0 || by > 2) continue;
                        for (int ax = 0; ax < 3; ++ax) {
                            int bx = v - ax; if (bx < 0 || bx > 2) continue;
                            acc += c2w[((oc * 5 + ic) * 3 + by) * 3 + bx]
                                 * c1w[(ic * 3 + ay) * 3 + ax];
                        }
                    }
            g_keff[t] = acc * 0.1f;
        } else {
            float acc = 0.f;
            for (int oc = 0; oc < 10; ++oc) {
                float t2 = c2b[oc];
                for (int ic = 0; ic < 5; ++ic) {
                    float sw = 0.f;
                    for (int bb = 0; bb < 9; ++bb) sw += c2w[(oc * 5 + ic) * 9 + bb];
                    t2 += c1b[ic] * sw;
                }
                acc += t2;
            }
            g_c = acc * 0.1f;
        }
    }
}

// ---------------- kernel A: fc1 + relu + ln1, and m = mean(x0) ---------------
__global__ void __launch_bounds__(256) kernelA(const float* __restrict__ x0,
    const float* __restrict__ fc1_w, const float* __restrict__ fc1_b,
    const float* __restrict__ ln1_g, const float* __restrict__ ln1_b)
{
    __shared__ float fw[PP * 3], fb[PP], lg[PP], lb[PP];
    int tid = threadIdx.x;
    for (int i = tid; i < PP * 3; i += 256) fw[i] = fc1_w[i];
    for (int i = tid; i < PP; i += 256) { fb[i] = fc1_b[i]; lg[i] = ln1_g[i]; lb[i] = ln1_b[i]; }
    __syncthreads();

    int lane = tid & 31, wid = tid >> 5;
    int ss = blockIdx.x * 8 + wid;          // one warp per sample
    const float* xp = x0 + (size_t)ss * 3;
    float xa = xp[0], xb = xp[1], xc = xp[2];
    if (lane == 0) g_m[ss] = (xa + xb + xc) * (1.f / 3.f);

    float v[13];
    float sum = 0.f, sq = 0.f;
#pragma unroll
    for (int k = 0; k < 13; ++k) {
        int q = lane + 32 * k;
        float h = 0.f;
        if (q < PP) {
            h = xa * fw[q * 3] + xb * fw[q * 3 + 1] + xc * fw[q * 3 + 2] + fb[q];
            h = fmaxf(h, 0.f);
        }
        v[k] = h; sum += h; sq += h * h;
    }
    for (int o = 16; o; o >>= 1) {
        sum += __shfl_xor_sync(~0u, sum, o);
        sq  += __shfl_xor_sync(~0u, sq, o);
    }
    float mu = sum * (1.f / PP);
    float var = sq * (1.f / PP) - mu * mu;
    float rs = rsqrtf(var + 1e-5f);
    float* hp = g_h1 + (size_t)ss * PP;
#pragma unroll
    for (int k = 0; k < 13; ++k) {
        int q = lane + 32 * k;
        if (q < PP) hp[q] = (v[k] - mu) * rs * lg[q] + lb[q];
    }
}

// ---------------- kernel B: fc2 GEMM + relu + ln2 + conv5x5 + sigmoid --------
#define BM 64
#define BK 16
#define SM_AS (BM * 20)        // [m][k] pad 20
#define SM_BS (BK * 404)       // [k][q] pad 404
#define SM_CS (BM * 401)       // [m][q] pad 401
__global__ void __launch_bounds__(256, 1) kernelB(
    const float* __restrict__ fc2_b, const float* __restrict__ ln2_g,
    const float* __restrict__ ln2_b, float* __restrict__ out)
{
    extern __shared__ float sm[];
    float* As  = sm;
    float* Bs  = As + SM_AS;
    float* Cs  = Bs + SM_BS;
    float* pb  = Cs + SM_CS;      // fc2_b [400]
    float* pg  = pb + PP;         // ln2_g
    float* pb2 = pg + PP;         // ln2_b
    float* ks  = pb2 + PP;        // keff[25] + c

    int tid = threadIdx.x;
    int s0 = blockIdx.x * BM;

    for (int q = tid; q < PP; q += 256) { pb[q] = fc2_b[q]; pg[q] = ln2_g[q]; pb2[q] = ln2_b[q]; }
    if (tid < 26) ks[tid] = (tid < 25) ? g_keff[tid] : g_c;

    int tr = tid >> 4, tc = tid & 15;
    float acc[4][25];
#pragma unroll
    for (int i = 0; i < 4; ++i)
#pragma unroll
        for (int j = 0; j < 25; ++j) acc[i][j] = 0.f;

    for (int kk = 0; kk < PP; kk += BK) {
        __syncthreads();
        {
            int mrow = tid >> 2, k4 = (tid & 3) * 4;
            float4 v = *(const float4*)(g_h1 + (size_t)(s0 + mrow) * PP + kk + k4);
            *(float4*)(As + mrow * 20 + k4) = v;
        }
        for (int f = tid; f < 1600; f += 256) {
            int krow = f / 100, q4 = (f % 100) * 4;
            float4 v = *(const float4*)(g_wT + (kk + krow) * PP + q4);
            *(float4*)(Bs + krow * 404 + q4) = v;
        }
        __syncthreads();
#pragma unroll
        for (int k = 0; k < BK; ++k) {
            float a[4], bq[25];
#pragma unroll
            for (int i = 0; i < 4; ++i) a[i] = As[(tr * 4 + i) * 20 + k];
#pragma unroll
            for (int j = 0; j < 25; ++j) bq[j] = Bs[k * 404 + tc * 25 + j];
#pragma unroll
            for (int i = 0; i < 4; ++i)
#pragma unroll
                for (int j = 0; j < 25; ++j) acc[i][j] += a[i] * bq[j];
        }
    }
    __syncthreads();

#pragma unroll
    for (int i = 0; i < 4; ++i)
#pragma unroll
        for (int j = 0; j < 25; ++j) {
            int q = tc * 25 + j;
            Cs[(tr * 4 + i) * 401 + q] = fmaxf(acc[i][j] + pb[q], 0.f);
        }
    __syncthreads();

    int lane = tid & 31, wid = tid >> 5;
    for (int r = wid * 8; r < wid * 8 + 8; ++r) {
        float sum = 0.f, sq = 0.f;
#pragma unroll
        for (int k = 0; k < 13; ++k) {
            int q = lane + 32 * k;
            if (q < PP) { float x = Cs[r * 401 + q]; sum += x; sq += x * x; }
        }
        for (int o = 16; o; o >>= 1) {
            sum += __shfl_xor_sync(~0u, sum, o);
            sq  += __shfl_xor_sync(~0u, sq, o);
        }
        float mu = sum * (1.f / PP);
        float var = sq * (1.f / PP) - mu * mu;
        float rs = rsqrtf(var + 1e-5f);
#pragma unroll
        for (int k = 0; k < 13; ++k) {
            int q = lane + 32 * k;
            if (q < PP) {
                float x = Cs[r * 401 + q];
                Cs[r * 401 + q] = (x - mu) * rs * pg[q] + pb2[q];
            }
        }
    }
    __syncthreads();

    int b = s0 >> 12;
    int sw = s0 & (SEQ - 1);
    float kreg[25];
#pragma unroll
    for (int d = 0; d < 25; ++d) kreg[d] = ks[d];
    float cc = ks[25];

    for (int pi = 0; pi < 2; ++pi) {
        int p = tid + pi * 256;
        if (p < PP) {
            int ii = p / 20, jj = p % 20;
            int nb[25];
#pragma unroll
            for (int d = 0; d < 25; ++d) {
                int du = d / 5 - 2, dv = d % 5 - 2;
                int y = (ii + du + 20) % 20;
                int x = (jj + dv + 20) % 20;
                nb[d] = y * 20 + x;
            }
            float* obase = out + ((size_t)(b * PP + p)) * SEQ + sw;
            for (int r8 = 0; r8 < BM; r8 += 8) {
                float o8[8];
#pragma unroll
                for (int rr = 0; rr < 8; ++rr) o8[rr] = cc;
#pragma unroll
                for (int d = 0; d < 25; ++d) {
                    float kv = kreg[d];
#pragma unroll
                    for (int rr = 0; rr < 8; ++rr)
                        o8[rr] += kv * Cs[(r8 + rr) * 401 + nb[d]];
                }
#pragma unroll
                for (int rr = 0; rr < 8; ++rr) o8[rr] = 1.f / (1.f + __expf(-o8[rr]));
                *(float4*)(obase + r8)     = make_float4(o8[0], o8[1], o8[2], o8[3]);
                *(float4*)(obase + r8 + 4) = make_float4(o8[4], o8[5], o8[6], o8[7]);
            }
        }
    }
}

// ---------------- selection: full-chip fixed-count iterations ---------------

// init: res = 1, v2 = m^2, sel = 0, done = 0
__global__ void init_sel_kernel()
{
    int b = blockIdx.x;
    int tid = threadIdx.x;
    for (int s = tid; s < SEQ; s += 256) {
        float m = g_m[b * SEQ + s];
        g_res[b * SEQ + s] = 1.f;
        g_v2[b * SEQ + s] = m * m;
    }
    for (int p = tid; p < PP; p += 256) g_sel[b * PP + p] = 0;
    if (tid == 0) g_done[b] = 0;
}

// one (b,p) row per block: act = sum_s w^2 * v2   (full-chip, HBM-bound ~8us)
__global__ void __launch_bounds__(256) act_iter_kernel(const float* __restrict__ w)
{
    int b = blockIdx.x / PP;
    int p = blockIdx.x % PP;
    if (g_done[b]) return;
    int tid = threadIdx.x;
    if (g_sel[b * PP + p]) { if (tid == 0) g_act[b * PP + p] = -1.f; return; }

    const float4* wp = (const float4*)(w + ((size_t)(b * PP + p)) * SEQ);
    const float4* vv = (const float4*)(g_v2 + (size_t)b * SEQ);
    float a = 0.f;
#pragma unroll
    for (int k = tid; k < SEQ / 4; k += 256) {
        float4 x = wp[k]; float4 y = vv[k];
        a += x.x * x.x * y.x + x.y * x.y * y.y + x.z * x.z * y.z + x.w * x.w * y.w;
    }
    // deterministic fixed-order reduction: warp shfl then smem tree
    for (int o = 16; o; o >>= 1) a += __shfl_xor_sync(~0u, a, o);
    __shared__ float ws[8];
    int lane = tid & 31, wid = tid >> 5;
    if (lane == 0) ws[wid] = a;
    __syncthreads();
    if (tid == 0) {
        float t = 0.f;
#pragma unroll
        for (int i = 0; i < 8; ++i) t += ws[i];
        g_act[b * PP + p] = t;
    }
}

// argmax + select + residual update + done flag + next v2, one block per batch
__global__ void __launch_bounds__(1024) upd_kernel(const float* __restrict__ w)
{
    int b = blockIdx.x;
    if (g_done[b]) return;
    int tid = threadIdx.x, lane = tid & 31, wid = tid >> 5;
    __shared__ float wvv[32];
    __shared__ int   wii[32];
    __shared__ float rsum[32];
    __shared__ int   s_pid;

    // argmax over 400, ties -> lowest index (matches jnp.argmax)
    float bv = -2.f; int bi = 0x7fffffff;
    for (int p = tid; p < PP; p += 1024) {
        float v = g_act[b * PP + p];
        if (v > bv || (v == bv && p < bi)) { bv = v; bi = p; }
    }
    for (int o = 16; o; o >>= 1) {
        float ov = __shfl_xor_sync(~0u, bv, o);
        int   oi = __shfl_xor_sync(~0u, bi, o);
        if (ov > bv || (ov == bv && oi < bi)) { bv = ov; bi = oi; }
    }
    if (lane == 0) { wvv[wid] = bv; wii[wid] = bi; }
    __syncthreads();
    if (tid == 0) {
        float fv = -2.f; int fi = 0x7fffffff;
#pragma unroll
        for (int i = 0; i < 32; ++i)
            if (wvv[i] > fv || (wvv[i] == fv && wii[i] < fi)) { fv = wvv[i]; fi = wii[i]; }
        s_pid = fi; g_sel[b * PP + fi] = 1;
    }
    __syncthreads();
    int pid = s_pid;

    // res update + mean + next v2 in one pass
    const float* row = w + ((size_t)(b * PP + pid)) * SEQ;
    float loc = 0.f;
    for (int s = tid; s < SEQ; s += 1024) {
        float r = g_res[b * SEQ + s] - row[s];
        r = r > 0.f ? r : 0.f;
        g_res[b * SEQ + s] = r;
        loc += r;
        float v = r * g_m[b * SEQ + s];
        g_v2[b * SEQ + s] = v * v;
    }
    for (int o = 16; o; o >>= 1) loc += __shfl_xor_sync(~0u, loc, o);
    if (lane == 0) rsum[wid] = loc;
    __syncthreads();
    if (tid == 0) {
        float t = 0.f;
#pragma unroll
        for (int i = 0; i < 32; ++i) t += rsum[i];
        if (t * (1.f / SEQ) < 0.05f) g_done[b] = 1;
    }
}

// ---------------- final scale: out *= sel ? 1 : 0.1 -------------------------
__global__ void scale_kernel(float* __restrict__ out)
{
    int idx = blockIdx.x * 256 + threadIdx.x;   // float4 index
    float4* o4 = (float4*)out;
    int bp = idx >> 10;                          // 4096/4 float4 per row
    float sc = g_sel[bp] ? 1.f : 0.1f;
    float4 v = o4[idx];
    v.x *= sc; v.y *= sc; v.z *= sc; v.w *= sc;
    o4[idx] = v;
}

// ---------------- launch --------------------------------------------------
extern "C" void kernel_launch(void* const* d_in, const int* in_sizes, int n_in,
                              void* d_out, int out_size)
{
    const float* x0     = (const float*)d_in[0];
    const float* fc1_w  = (const float*)d_in[1];
    const float* fc1_b  = (const float*)d_in[2];
    const float* ln1_g  = (const float*)d_in[3];
    const float* ln1_b  = (const float*)d_in[4];
    const float* fc2_w  = (const float*)d_in[5];
    const float* fc2_b  = (const float*)d_in[6];
    const float* ln2_g  = (const float*)d_in[7];
    const float* ln2_b  = (const float*)d_in[8];
    const float* c1w    = (const float*)d_in[9];
    const float* c1b    = (const float*)d_in[10];
    const float* c2w    = (const float*)d_in[11];
    const float* c2b    = (const float*)d_in[12];
    float* out = (float*)d_out;

    const int smemB = (SM_AS + SM_BS + SM_CS + 3 * PP + 26) * sizeof(float);
    cudaFuncSetAttribute(kernelB, cudaFuncAttributeMaxDynamicSharedMemorySize, smemB);

    prep_kernel<<<625, 256>>>(fc2_w, c1w, c1b, c2w, c2b);
    kernelA<<<NSAMP / 8, 256>>>(x0, fc1_w, fc1_b, ln1_g, ln1_b);
    kernelB<<<NSAMP / BM, 256, smemB>>>(fc2_b, ln2_g, ln2_b, out);
    init_sel_kernel<<<BATCH, 256>>>();
    for (int it = 0; it < ITERS; ++it) {
        act_iter_kernel<<<BATCH * PP, 256>>>(out);
        upd_kernel<<<BATCH, 1024>>>(out);
    }
    scale_kernel<<<(NSAMP * PP / 4) / 256, 256>>>(out);
}

// round 3
// speedup vs baseline: 1.1880x; 1.0857x over previous
#include <cuda_runtime.h>
#include <math.h>

// Problem constants
#define BATCH 8
#define SEQ   4096
#define DIM   3
#define PP    400          // 20x20
#define QPAD  416          // N padded to 16x26 for f32x2 pairs
#define NSAMP (BATCH*SEQ)  // 32768
#define ITERS 12           // fixed selection iteration count (early-exit via flags)

typedef unsigned long long u64;

__device__ __forceinline__ u64 pack2(float lo, float hi) {
    u64 r; asm("mov.b64 %0,{%1,%2};" : "=l"(r) : "f"(lo), "f"(hi)); return r;
}
__device__ __forceinline__ void fma2(u64& d, u64 a, u64 b) {
    asm("fma.rn.f32x2 %0,%1,%2,%0;" : "+l"(d) : "l"(a), "l"(b));
}

// ---------------- scratch (static __device__, no allocations) ----------------
__device__ float g_h1[NSAMP * PP];      // ln1 output, (sample, q)  52 MB
__device__ float g_m[NSAMP];            // mean over D of x0
__device__ float g_wT[PP * QPAD];       // fc2_w transposed + N-padded: [k][q]
__device__ float g_keff[25];            // composed 5x5 circular kernel
__device__ float g_c;                   // composed bias (after channel mean)
__device__ float g_act[BATCH * PP];     // per-iteration activities
__device__ int   g_sel[BATCH * PP];     // selection mask
__device__ int   g_done[BATCH];         // per-batch early-exit flag
__device__ float g_res[BATCH * SEQ];    // residual
__device__ float g_v2[BATCH * SEQ];     // (res*m)^2

// ---------------- prep: transpose+pad fc2_w, compose conv1*conv2 -------------
__global__ void prep_kernel(const float* __restrict__ fc2_w,
                            const float* __restrict__ c1w, const float* __restrict__ c1b,
                            const float* __restrict__ c2w, const float* __restrict__ c2b)
{
    int idx = blockIdx.x * 256 + threadIdx.x;
    if (idx < PP * QPAD) {
        int k = idx / QPAD, q = idx % QPAD;
        g_wT[idx] = (q < PP) ? fc2_w[q * PP + k] : 0.f;
    }
    if (blockIdx.x == 0 && threadIdx.x < 26) {
        int t = threadIdx.x;
        if (t < 25) {
            int u = t / 5, v = t % 5;
            float acc = 0.f;
            for (int oc = 0; oc < 10; ++oc)
                for (int ic = 0; ic < 5; ++ic)
                    for (int ay = 0; ay < 3; ++ay) {
                        int by = u - ay; if (by < 0 || by > 2) continue;
                        for (int ax = 0; ax < 3; ++ax) {
                            int bx = v - ax; if (bx < 0 || bx > 2) continue;
                            acc += c2w[((oc * 5 + ic) * 3 + by) * 3 + bx]
                                 * c1w[(ic * 3 + ay) * 3 + ax];
                        }
                    }
            g_keff[t] = acc * 0.1f;
        } else {
            float acc = 0.f;
            for (int oc = 0; oc < 10; ++oc) {
                float t2 = c2b[oc];
                for (int ic = 0; ic < 5; ++ic) {
                    float sw = 0.f;
                    for (int bb = 0; bb < 9; ++bb) sw += c2w[(oc * 5 + ic) * 9 + bb];
                    t2 += c1b[ic] * sw;
                }
                acc += t2;
            }
            g_c = acc * 0.1f;
        }
    }
}

// ---------------- kernel A: fc1 + relu + ln1, and m = mean(x0) ---------------
__global__ void __launch_bounds__(256) kernelA(const float* __restrict__ x0,
    const float* __restrict__ fc1_w, const float* __restrict__ fc1_b,
    const float* __restrict__ ln1_g, const float* __restrict__ ln1_b)
{
    __shared__ float fw[PP * 3], fb[PP], lg[PP], lb[PP];
    int tid = threadIdx.x;
    for (int i = tid; i < PP * 3; i += 256) fw[i] = fc1_w[i];
    for (int i = tid; i < PP; i += 256) { fb[i] = fc1_b[i]; lg[i] = ln1_g[i]; lb[i] = ln1_b[i]; }
    __syncthreads();

    int lane = tid & 31, wid = tid >> 5;
    int ss = blockIdx.x * 8 + wid;          // one warp per sample
    const float* xp = x0 + (size_t)ss * 3;
    float xa = xp[0], xb = xp[1], xc = xp[2];
    if (lane == 0) g_m[ss] = (xa + xb + xc) * (1.f / 3.f);

    float v[13];
    float sum = 0.f, sq = 0.f;
#pragma unroll
    for (int k = 0; k < 13; ++k) {
        int q = lane + 32 * k;
        float h = 0.f;
        if (q < PP) {
            h = xa * fw[q * 3] + xb * fw[q * 3 + 1] + xc * fw[q * 3 + 2] + fb[q];
            h = fmaxf(h, 0.f);
        }
        v[k] = h; sum += h; sq += h * h;
    }
    for (int o = 16; o; o >>= 1) {
        sum += __shfl_xor_sync(~0u, sum, o);
        sq  += __shfl_xor_sync(~0u, sq, o);
    }
    float mu = sum * (1.f / PP);
    float var = sq * (1.f / PP) - mu * mu;
    float rs = rsqrtf(var + 1e-5f);
    float* hp = g_h1 + (size_t)ss * PP;
#pragma unroll
    for (int k = 0; k < 13; ++k) {
        int q = lane + 32 * k;
        if (q < PP) hp[q] = (v[k] - mu) * rs * lg[q] + lb[q];
    }
}

// ---------------- kernel B: fc2 GEMM (f32x2) + relu + ln2 + conv5x5 + sigmoid
#define BM 64
#define BK 16
#define SM_AS (BM * 20)          // [m][k] pad 20
#define SM_BS (BK * QPAD)        // [k][q] : 16 x 416
#define SM_CS (BM * 401)         // [m][q] pad 401
__global__ void __launch_bounds__(256, 1) kernelB(
    const float* __restrict__ fc2_b, const float* __restrict__ ln2_g,
    const float* __restrict__ ln2_b, float* __restrict__ out)
{
    extern __shared__ float sm[];
    float* As  = sm;
    float* Bs  = As + SM_AS;
    float* Cs  = Bs + SM_BS;
    float* pb  = Cs + SM_CS;      // fc2_b [400]
    float* pg  = pb + PP;         // ln2_g
    float* pb2 = pg + PP;         // ln2_b
    float* ks  = pb2 + PP;        // keff[25] + c

    int tid = threadIdx.x;
    int s0 = blockIdx.x * BM;

    for (int q = tid; q < PP; q += 256) { pb[q] = fc2_b[q]; pg[q] = ln2_g[q]; pb2[q] = ln2_b[q]; }
    if (tid < 26) ks[tid] = (tid < 25) ? g_keff[tid] : g_c;

    int tr = tid >> 4, tc = tid & 15;     // 16x16 threads: 4 M-rows x 26 N-cols each
    u64 acc[4][13];
#pragma unroll
    for (int i = 0; i < 4; ++i)
#pragma unroll
        for (int j = 0; j < 13; ++j) acc[i][j] = 0ull;

    for (int kk = 0; kk < PP; kk += BK) {
        __syncthreads();
        {   // load As: 64 rows x 16 k, 256 float4
            int mrow = tid >> 2, k4 = (tid & 3) * 4;
            float4 v = *(const float4*)(g_h1 + (size_t)(s0 + mrow) * PP + kk + k4);
            *(float4*)(As + mrow * 20 + k4) = v;
        }
        for (int f = tid; f < (BK * QPAD / 4); f += 256) {   // Bs: 16 x 416, 1664 float4
            int krow = f / (QPAD / 4), q4 = (f % (QPAD / 4)) * 4;
            float4 v = *(const float4*)(g_wT + (size_t)(kk + krow) * QPAD + q4);
            *(float4*)(Bs + krow * QPAD + q4) = v;
        }
        __syncthreads();
#pragma unroll
        for (int k = 0; k < BK; ++k) {
            u64 ap[4], bv[13];
#pragma unroll
            for (int i = 0; i < 4; ++i) {
                float av = As[(tr * 4 + i) * 20 + k];
                ap[i] = pack2(av, av);
            }
#pragma unroll
            for (int j = 0; j < 13; ++j)
                bv[j] = *(const u64*)(Bs + k * QPAD + tc * 26 + 2 * j);
#pragma unroll
            for (int i = 0; i < 4; ++i)
#pragma unroll
                for (int j = 0; j < 13; ++j) fma2(acc[i][j], ap[i], bv[j]);
        }
    }
    __syncthreads();

    // bias + relu -> Cs  (guard q >= 400 pad lanes)
#pragma unroll
    for (int i = 0; i < 4; ++i)
#pragma unroll
        for (int j = 0; j < 13; ++j) {
            float2 v = *(float2*)&acc[i][j];
            int q0 = tc * 26 + 2 * j;
            int row = (tr * 4 + i) * 401;
            if (q0 < PP)     Cs[row + q0]     = fmaxf(v.x + pb[q0], 0.f);
            if (q0 + 1 < PP) Cs[row + q0 + 1] = fmaxf(v.y + pb[q0 + 1], 0.f);
        }
    __syncthreads();

    // LN2 per sample row (8 warps x 8 rows)
    int lane = tid & 31, wid = tid >> 5;
    for (int r = wid * 8; r < wid * 8 + 8; ++r) {
        float sum = 0.f, sq = 0.f;
#pragma unroll
        for (int k = 0; k < 13; ++k) {
            int q = lane + 32 * k;
            if (q < PP) { float x = Cs[r * 401 + q]; sum += x; sq += x * x; }
        }
        for (int o = 16; o; o >>= 1) {
            sum += __shfl_xor_sync(~0u, sum, o);
            sq  += __shfl_xor_sync(~0u, sq, o);
        }
        float mu = sum * (1.f / PP);
        float var = sq * (1.f / PP) - mu * mu;
        float rs = rsqrtf(var + 1e-5f);
#pragma unroll
        for (int k = 0; k < 13; ++k) {
            int q = lane + 32 * k;
            if (q < PP) {
                float x = Cs[r * 401 + q];
                Cs[r * 401 + q] = (x - mu) * rs * pg[q] + pb2[q];
            }
        }
    }
    __syncthreads();

    // 5x5 circular conv + sigmoid + transposed write
    int b = s0 >> 12;          // SEQ=4096
    int sw = s0 & (SEQ - 1);
    float kreg[25];
#pragma unroll
    for (int d = 0; d < 25; ++d) kreg[d] = ks[d];
    float cc = ks[25];

    for (int pi = 0; pi < 2; ++pi) {
        int p = tid + pi * 256;
        if (p < PP) {
            int ii = p / 20, jj = p % 20;
            int nb[25];
#pragma unroll
            for (int d = 0; d < 25; ++d) {
                int du = d / 5 - 2, dv = d % 5 - 2;
                int y = (ii + du + 20) % 20;
                int x = (jj + dv + 20) % 20;
                nb[d] = y * 20 + x;
            }
            float* obase = out + ((size_t)(b * PP + p)) * SEQ + sw;
            for (int r8 = 0; r8 < BM; r8 += 8) {
                float o8[8];
#pragma unroll
                for (int rr = 0; rr < 8; ++rr) o8[rr] = cc;
#pragma unroll
                for (int d = 0; d < 25; ++d) {
                    float kv = kreg[d];
#pragma unroll
                    for (int rr = 0; rr < 8; ++rr)
                        o8[rr] += kv * Cs[(r8 + rr) * 401 + nb[d]];
                }
#pragma unroll
                for (int rr = 0; rr < 8; ++rr) o8[rr] = 1.f / (1.f + __expf(-o8[rr]));
                *(float4*)(obase + r8)     = make_float4(o8[0], o8[1], o8[2], o8[3]);
                *(float4*)(obase + r8 + 4) = make_float4(o8[4], o8[5], o8[6], o8[7]);
            }
        }
    }
}

// ---------------- selection: full-chip fixed-count iterations ---------------

// init: res = 1, v2 = m^2, sel = 0, done = 0
__global__ void init_sel_kernel()
{
    int b = blockIdx.x;
    int tid = threadIdx.x;
    for (int s = tid; s < SEQ; s += 256) {
        float m = g_m[b * SEQ + s];
        g_res[b * SEQ + s] = 1.f;
        g_v2[b * SEQ + s] = m * m;
    }
    for (int p = tid; p < PP; p += 256) g_sel[b * PP + p] = 0;
    if (tid == 0) g_done[b] = 0;
}

// one (b,p) row per block: act = sum_s w^2 * v2   (full-chip, HBM-bound)
__global__ void __launch_bounds__(256) act_iter_kernel(const float* __restrict__ w)
{
    int b = blockIdx.x / PP;
    int p = blockIdx.x % PP;
    if (g_done[b]) return;
    int tid = threadIdx.x;
    if (g_sel[b * PP + p]) { if (tid == 0) g_act[b * PP + p] = -1.f; return; }

    const float4* wp = (const float4*)(w + ((size_t)(b * PP + p)) * SEQ);
    const float4* vv = (const float4*)(g_v2 + (size_t)b * SEQ);
    float a = 0.f;
#pragma unroll
    for (int k = tid; k < SEQ / 4; k += 256) {
        float4 x = wp[k]; float4 y = vv[k];
        a += x.x * x.x * y.x + x.y * x.y * y.y + x.z * x.z * y.z + x.w * x.w * y.w;
    }
    // deterministic fixed-order reduction
    for (int o = 16; o; o >>= 1) a += __shfl_xor_sync(~0u, a, o);
    __shared__ float ws[8];
    int lane = tid & 31, wid = tid >> 5;
    if (lane == 0) ws[wid] = a;
    __syncthreads();
    if (tid == 0) {
        float t = 0.f;
#pragma unroll
        for (int i = 0; i < 8; ++i) t += ws[i];
        g_act[b * PP + p] = t;
    }
}

// argmax + select + residual update + done flag + next v2, one block per batch
__global__ void __launch_bounds__(1024) upd_kernel(const float* __restrict__ w)
{
    int b = blockIdx.x;
    if (g_done[b]) return;
    int tid = threadIdx.x, lane = tid & 31, wid = tid >> 5;
    __shared__ float wvv[32];
    __shared__ int   wii[32];
    __shared__ float rsum[32];
    __shared__ int   s_pid;

    // argmax over 400, ties -> lowest index (matches jnp.argmax)
    float bv = -2.f; int bi = 0x7fffffff;
    for (int p = tid; p < PP; p += 1024) {
        float v = g_act[b * PP + p];
        if (v > bv || (v == bv && p < bi)) { bv = v; bi = p; }
    }
    for (int o = 16; o; o >>= 1) {
        float ov = __shfl_xor_sync(~0u, bv, o);
        int   oi = __shfl_xor_sync(~0u, bi, o);
        if (ov > bv || (ov == bv && oi < bi)) { bv = ov; bi = oi; }
    }
    if (lane == 0) { wvv[wid] = bv; wii[wid] = bi; }
    __syncthreads();
    if (tid == 0) {
        float fv = -2.f; int fi = 0x7fffffff;
#pragma unroll
        for (int i = 0; i < 32; ++i)
            if (wvv[i] > fv || (wvv[i] == fv && wii[i] < fi)) { fv = wvv[i]; fi = wii[i]; }
        s_pid = fi; g_sel[b * PP + fi] = 1;
    }
    __syncthreads();
    int pid = s_pid;

    // res update + mean + next v2 in one pass
    const float* row = w + ((size_t)(b * PP + pid)) * SEQ;
    float loc = 0.f;
    for (int s = tid; s < SEQ; s += 1024) {
        float r = g_res[b * SEQ + s] - row[s];
        r = r > 0.f ? r : 0.f;
        g_res[b * SEQ + s] = r;
        loc += r;
        float v = r * g_m[b * SEQ + s];
        g_v2[b * SEQ + s] = v * v;
    }
    for (int o = 16; o; o >>= 1) loc += __shfl_xor_sync(~0u, loc, o);
    if (lane == 0) rsum[wid] = loc;
    __syncthreads();
    if (tid == 0) {
        float t = 0.f;
#pragma unroll
        for (int i = 0; i < 32; ++i) t += rsum[i];
        if (t * (1.f / SEQ) < 0.05f) g_done[b] = 1;
    }
}

// ---------------- final scale: out *= sel ? 1 : 0.1 -------------------------
__global__ void scale_kernel(float* __restrict__ out)
{
    int idx = blockIdx.x * 256 + threadIdx.x;   // float4 index
    float4* o4 = (float4*)out;
    int bp = idx >> 10;                          // 4096/4 float4 per row
    float sc = g_sel[bp] ? 1.f : 0.1f;
    float4 v = o4[idx];
    v.x *= sc; v.y *= sc; v.z *= sc; v.w *= sc;
    o4[idx] = v;
}

// ---------------- launch --------------------------------------------------
extern "C" void kernel_launch(void* const* d_in, const int* in_sizes, int n_in,
                              void* d_out, int out_size)
{
    const float* x0     = (const float*)d_in[0];
    const float* fc1_w  = (const float*)d_in[1];
    const float* fc1_b  = (const float*)d_in[2];
    const float* ln1_g  = (const float*)d_in[3];
    const float* ln1_b  = (const float*)d_in[4];
    const float* fc2_w  = (const float*)d_in[5];
    const float* fc2_b  = (const float*)d_in[6];
    const float* ln2_g  = (const float*)d_in[7];
    const float* ln2_b  = (const float*)d_in[8];
    const float* c1w    = (const float*)d_in[9];
    const float* c1b    = (const float*)d_in[10];
    const float* c2w    = (const float*)d_in[11];
    const float* c2b    = (const float*)d_in[12];
    float* out = (float*)d_out;

    const int smemB = (SM_AS + SM_BS + SM_CS + 3 * PP + 26) * sizeof(float);
    cudaFuncSetAttribute(kernelB, cudaFuncAttributeMaxDynamicSharedMemorySize, smemB);

    prep_kernel<<<(PP * QPAD + 255) / 256, 256>>>(fc2_w, c1w, c1b, c2w, c2b);
    kernelA<<<NSAMP / 8, 256>>>(x0, fc1_w, fc1_b, ln1_g, ln1_b);
    kernelB<<<NSAMP / BM, 256, smemB>>>(fc2_b, ln2_g, ln2_b, out);
    init_sel_kernel<<<BATCH, 256>>>();
    for (int it = 0; it < ITERS; ++it) {
        act_iter_kernel<<<BATCH * PP, 256>>>(out);
        upd_kernel<<<BATCH, 1024>>>(out);
    }
    scale_kernel<<<(NSAMP * PP / 4) / 256, 256>>>(out);
}

// round 4
// speedup vs baseline: 1.3190x; 1.1102x over previous
#include <cuda_runtime.h>
#include <math.h>

// Problem constants
#define BATCH 8
#define SEQ   4096
#define PP    400          // 20x20
#define QPAD  416          // N padded to 16x26 for f32x2 pairs
#define NSAMP (BATCH*SEQ)  // 32768
#define ITERS 12           // max selection iterations (early-exit inside kernel)
#define NBLK  256          // persistent selection grid (must be co-resident)

typedef unsigned long long u64;

__device__ __forceinline__ u64 pack2(float lo, float hi) {
    u64 r; asm("mov.b64 %0,{%1,%2};" : "=l"(r) : "f"(lo), "f"(hi)); return r;
}
__device__ __forceinline__ void fma2(u64& d, u64 a, u64 b) {
    asm("fma.rn.f32x2 %0,%1,%2,%0;" : "+l"(d) : "l"(a), "l"(b));
}

// ---------------- scratch (static __device__, no allocations) ----------------
__device__ float g_m[NSAMP];            // mean over D of x0
__device__ float g_wT[PP * QPAD];       // fc2_w transposed + N-padded: [k][q]
__device__ float g_keff[25];            // composed 5x5 circular kernel
__device__ float g_c;                   // composed bias (after channel mean)
__device__ float g_act[BATCH * PP];     // per-iteration activities
__device__ int   g_sel[BATCH * PP];     // selection mask
__device__ int   g_done[BATCH];         // per-batch early-exit flag
__device__ float g_res[BATCH * SEQ];    // residual
__device__ float g_v2[BATCH * SEQ];     // (res*m)^2
__device__ unsigned g_bar;              // grid barrier counter (reset by prep)

// ---------------- prep: transpose+pad fc2_w, compose conv1*conv2 -------------
__global__ void prep_kernel(const float* __restrict__ fc2_w,
                            const float* __restrict__ c1w, const float* __restrict__ c1b,
                            const float* __restrict__ c2w, const float* __restrict__ c2b)
{
    int idx = blockIdx.x * 256 + threadIdx.x;
    if (idx < PP * QPAD) {
        int k = idx / QPAD, q = idx % QPAD;
        g_wT[idx] = (q < PP) ? fc2_w[q * PP + k] : 0.f;
    }
    if (blockIdx.x == 0 && threadIdx.x == 0) g_bar = 0u;   // reset grid barrier
    if (blockIdx.x == 0 && threadIdx.x < 26) {
        int t = threadIdx.x;
        if (t < 25) {
            int u = t / 5, v = t % 5;
            float acc = 0.f;
            for (int oc = 0; oc < 10; ++oc)
                for (int ic = 0; ic < 5; ++ic)
                    for (int ay = 0; ay < 3; ++ay) {
                        int by = u - ay; if (by < 0 || by > 2) continue;
                        for (int ax = 0; ax < 3; ++ax) {
                            int bx = v - ax; if (bx < 0 || bx > 2) continue;
                            acc += c2w[((oc * 5 + ic) * 3 + by) * 3 + bx]
                                 * c1w[(ic * 3 + ay) * 3 + ax];
                        }
                    }
            g_keff[t] = acc * 0.1f;
        } else {
            float acc = 0.f;
            for (int oc = 0; oc < 10; ++oc) {
                float t2 = c2b[oc];
                for (int ic = 0; ic < 5; ++ic) {
                    float sw = 0.f;
                    for (int bb = 0; bb < 9; ++bb) sw += c2w[(oc * 5 + ic) * 9 + bb];
                    t2 += c1b[ic] * sw;
                }
                acc += t2;
            }
            g_c = acc * 0.1f;
        }
    }
}

// ---- kernel B: fc1+ln1 (fused) + fc2 GEMM (f32x2) + ln2 + conv + sigmoid*0.1
#define BM 64
#define BK 16
#define AH_STRIDE 404
#define SM_AH (BM * AH_STRIDE)       // h1 tile [m][k], later reused as Cs [m][q]
#define SM_BS (BK * QPAD)            // 16 x 416
#define SM_TOTAL_F (SM_AH + SM_BS + 1200 + 6*PP + 26)

__global__ void __launch_bounds__(256, 1) kernelB(
    const float* __restrict__ x0,
    const float* __restrict__ fc1_w, const float* __restrict__ fc1_b,
    const float* __restrict__ ln1_g, const float* __restrict__ ln1_b,
    const float* __restrict__ fc2_b, const float* __restrict__ ln2_g,
    const float* __restrict__ ln2_b, float* __restrict__ out)
{
    extern __shared__ float sm[];
    float* Ah  = sm;                   // [64][404]: h1, then Cs
    float* Bs  = Ah + SM_AH;           // [16][416]
    float* fw  = Bs + SM_BS;           // fc1_w 400x3
    float* fb  = fw + 1200;
    float* l1g = fb + PP;
    float* l1b = l1g + PP;
    float* pb  = l1b + PP;             // fc2_b
    float* pg  = pb + PP;              // ln2_g
    float* pb2 = pg + PP;              // ln2_b
    float* ks  = pb2 + PP;             // keff[25] + c

    int tid = threadIdx.x;
    int lane = tid & 31, wid = tid >> 5;
    int s0 = blockIdx.x * BM;

    for (int i = tid; i < 1200; i += 256) fw[i] = fc1_w[i];
    for (int i = tid; i < PP; i += 256) {
        fb[i] = fc1_b[i]; l1g[i] = ln1_g[i]; l1b[i] = ln1_b[i];
        pb[i] = fc2_b[i]; pg[i] = ln2_g[i]; pb2[i] = ln2_b[i];
    }
    if (tid < 26) ks[tid] = (tid < 25) ? g_keff[tid] : g_c;
    __syncthreads();

    // ---- fused fc1 + relu + ln1 into Ah (one warp per sample, 8 rounds) ----
    for (int r = wid; r < BM; r += 8) {
        int ss = s0 + r;
        const float* xp = x0 + (size_t)ss * 3;
        float xa = xp[0], xb = xp[1], xc = xp[2];
        if (lane == 0) g_m[ss] = (xa + xb + xc) * (1.f / 3.f);
        float v[13];
        float sum = 0.f, sq = 0.f;
#pragma unroll
        for (int k = 0; k < 13; ++k) {
            int q = lane + 32 * k;
            float h = 0.f;
            if (q < PP) {
                h = xa * fw[q * 3] + xb * fw[q * 3 + 1] + xc * fw[q * 3 + 2] + fb[q];
                h = fmaxf(h, 0.f);
            }
            v[k] = h; sum += h; sq += h * h;
        }
        for (int o = 16; o; o >>= 1) {
            sum += __shfl_xor_sync(~0u, sum, o);
            sq  += __shfl_xor_sync(~0u, sq, o);
        }
        float mu = sum * (1.f / PP);
        float var = sq * (1.f / PP) - mu * mu;
        float rs = rsqrtf(var + 1e-5f);
#pragma unroll
        for (int k = 0; k < 13; ++k) {
            int q = lane + 32 * k;
            if (q < PP) Ah[r * AH_STRIDE + q] = (v[k] - mu) * rs * l1g[q] + l1b[q];
        }
    }
    __syncthreads();

    // ---- fc2 GEMM mainloop (f32x2), A resident in smem ----
    int tr = tid >> 4, tc = tid & 15;     // 4 M-rows x 26 N-cols per thread
    u64 acc[4][13];
#pragma unroll
    for (int i = 0; i < 4; ++i)
#pragma unroll
        for (int j = 0; j < 13; ++j) acc[i][j] = 0ull;

    for (int kk = 0; kk < PP; kk += BK) {
        __syncthreads();
        for (int f = tid; f < (BK * QPAD / 4); f += 256) {   // Bs: 16 x 416
            int krow = f / (QPAD / 4), q4 = (f % (QPAD / 4)) * 4;
            float4 v = *(const float4*)(g_wT + (size_t)(kk + krow) * QPAD + q4);
            *(float4*)(Bs + krow * QPAD + q4) = v;
        }
        __syncthreads();
#pragma unroll
        for (int k = 0; k < BK; ++k) {
            u64 ap[4], bv[13];
#pragma unroll
            for (int i = 0; i < 4; ++i) {
                float av = Ah[(tr * 4 + i) * AH_STRIDE + kk + k];
                ap[i] = pack2(av, av);
            }
#pragma unroll
            for (int j = 0; j < 13; ++j)
                bv[j] = *(const u64*)(Bs + k * QPAD + tc * 26 + 2 * j);
#pragma unroll
            for (int i = 0; i < 4; ++i)
#pragma unroll
                for (int j = 0; j < 13; ++j) fma2(acc[i][j], ap[i], bv[j]);
        }
    }
    __syncthreads();

    // ---- bias + relu -> Cs (overlay Ah) ----
    float* Cs = Ah;
#pragma unroll
    for (int i = 0; i < 4; ++i)
#pragma unroll
        for (int j = 0; j < 13; ++j) {
            float2 v = *(float2*)&acc[i][j];
            int q0 = tc * 26 + 2 * j;
            int row = (tr * 4 + i) * AH_STRIDE;
            if (q0 < PP)     Cs[row + q0]     = fmaxf(v.x + pb[q0], 0.f);
            if (q0 + 1 < PP) Cs[row + q0 + 1] = fmaxf(v.y + pb[q0 + 1], 0.f);
        }
    __syncthreads();

    // ---- LN2 per sample row (8 warps x 8 rows) ----
    for (int r = wid * 8; r < wid * 8 + 8; ++r) {
        float sum = 0.f, sq = 0.f;
#pragma unroll
        for (int k = 0; k < 13; ++k) {
            int q = lane + 32 * k;
            if (q < PP) { float x = Cs[r * AH_STRIDE + q]; sum += x; sq += x * x; }
        }
        for (int o = 16; o; o >>= 1) {
            sum += __shfl_xor_sync(~0u, sum, o);
            sq  += __shfl_xor_sync(~0u, sq, o);
        }
        float mu = sum * (1.f / PP);
        float var = sq * (1.f / PP) - mu * mu;
        float rs = rsqrtf(var + 1e-5f);
#pragma unroll
        for (int k = 0; k < 13; ++k) {
            int q = lane + 32 * k;
            if (q < PP) {
                float x = Cs[r * AH_STRIDE + q];
                Cs[r * AH_STRIDE + q] = (x - mu) * rs * pg[q] + pb2[q];
            }
        }
    }
    __syncthreads();

    // ---- 5x5 circular conv + 0.1*sigmoid + transposed write ----
    int b = s0 >> 12;          // SEQ=4096
    int sw = s0 & (SEQ - 1);
    float kreg[25];
#pragma unroll
    for (int d = 0; d < 25; ++d) kreg[d] = ks[d];
    float cc = ks[25];

    for (int pi = 0; pi < 2; ++pi) {
        int p = tid + pi * 256;
        if (p < PP) {
            int ii = p / 20, jj = p % 20;
            int nb[25];
#pragma unroll
            for (int d = 0; d < 25; ++d) {
                int du = d / 5 - 2, dv = d % 5 - 2;
                int y = (ii + du + 20) % 20;
                int x = (jj + dv + 20) % 20;
                nb[d] = y * 20 + x;
            }
            float* obase = out + ((size_t)(b * PP + p)) * SEQ + sw;
            for (int r8 = 0; r8 < BM; r8 += 8) {
                float o8[8];
#pragma unroll
                for (int rr = 0; rr < 8; ++rr) o8[rr] = cc;
#pragma unroll
                for (int d = 0; d < 25; ++d) {
                    float kv = kreg[d];
#pragma unroll
                    for (int rr = 0; rr < 8; ++rr)
                        o8[rr] += kv * Cs[(r8 + rr) * AH_STRIDE + nb[d]];
                }
                // store 0.1*sigmoid; selected rows rescaled x10 later
#pragma unroll
                for (int rr = 0; rr < 8; ++rr) o8[rr] = 0.1f / (1.f + __expf(-o8[rr]));
                *(float4*)(obase + r8)     = make_float4(o8[0], o8[1], o8[2], o8[3]);
                *(float4*)(obase + r8 + 4) = make_float4(o8[4], o8[5], o8[6], o8[7]);
            }
        }
    }
}

// ---------------- persistent selection: one launch, grid barriers -----------
__device__ __forceinline__ void gbar(unsigned& target)
{
    __syncthreads();
    __threadfence();                        // flush writes (gpu scope)
    if (threadIdx.x == 0) {
        atomicAdd(&g_bar, 1u);
        while (*(volatile unsigned*)&g_bar < target) { }
    }
    __syncthreads();
    __threadfence();                        // invalidate L1D for fresh reads
}

__global__ void __launch_bounds__(256) select_persistent(float* __restrict__ out)
{
    int b = blockIdx.x & 7;        // batch
    int g = blockIdx.x >> 3;       // 0..31 within batch
    int tid = threadIdx.x, lane = tid & 31, wid = tid >> 5;
    unsigned target = 0;
    __shared__ float ws[8];
    __shared__ float wvv[8];
    __shared__ int   wii[8];
    __shared__ float rsum[8];
    __shared__ int   s_pid, s_brk;

    // ---- init slices ----
    if (g < 16) {
        int s = g * 256 + tid;     // covers 4096
        float m = g_m[b * SEQ + s];
        g_res[b * SEQ + s] = 1.f;
        g_v2[b * SEQ + s] = m * m;
    } else if (g == 16 || g == 17) {
        int p = (g - 16) * 256 + tid;
        if (p < PP) g_sel[b * PP + p] = 0;
    } else if (g == 18 && tid == 0) {
        g_done[b] = 0;
    }
    target += NBLK; gbar(target);

    for (int it = 0; it < ITERS; ++it) {
        // ---- activity phase: 32 blocks x ~13 rows each ----
        if (!g_done[b]) {
            const float4* vv = (const float4*)(g_v2 + (size_t)b * SEQ);
            for (int p = g; p < PP; p += 32) {
                if (g_sel[b * PP + p]) {
                    if (tid == 0) g_act[b * PP + p] = -1.f;
                    continue;
                }
                const float4* wp = (const float4*)(out + ((size_t)(b * PP + p)) * SEQ);
                float a = 0.f;
#pragma unroll
                for (int j = 0; j < 4; ++j) {
                    int k = tid + 256 * j;
                    float4 x = wp[k]; float4 y = vv[k];
                    a += x.x * x.x * y.x + x.y * x.y * y.y
                       + x.z * x.z * y.z + x.w * x.w * y.w;
                }
                for (int o = 16; o; o >>= 1) a += __shfl_xor_sync(~0u, a, o);
                if (lane == 0) ws[wid] = a;
                __syncthreads();
                if (tid == 0) {
                    float t = 0.f;
#pragma unroll
                    for (int i = 0; i < 8; ++i) t += ws[i];
                    g_act[b * PP + p] = t;
                }
                __syncthreads();
            }
        }
        target += NBLK; gbar(target);

        // ---- update phase: leader block per batch ----
        if (g == 0 && !g_done[b]) {
            float bv = -2.f; int bi = 0x7fffffff;
            for (int p = tid; p < PP; p += 256) {
                float v = g_act[b * PP + p];
                if (v > bv || (v == bv && p < bi)) { bv = v; bi = p; }
            }
            for (int o = 16; o; o >>= 1) {
                float ov = __shfl_xor_sync(~0u, bv, o);
                int   oi = __shfl_xor_sync(~0u, bi, o);
                if (ov > bv || (ov == bv && oi < bi)) { bv = ov; bi = oi; }
            }
            if (lane == 0) { wvv[wid] = bv; wii[wid] = bi; }
            __syncthreads();
            if (tid == 0) {
                float fv = -2.f; int fi = 0x7fffffff;
#pragma unroll
                for (int i = 0; i < 8; ++i)
                    if (wvv[i] > fv || (wvv[i] == fv && wii[i] < fi)) { fv = wvv[i]; fi = wii[i]; }
                s_pid = fi; g_sel[b * PP + fi] = 1;
            }
            __syncthreads();
            int pid = s_pid;

            const float* row = out + ((size_t)(b * PP + pid)) * SEQ;  // 0.1*w
            float loc = 0.f;
            for (int s = tid; s < SEQ; s += 256) {
                float r = g_res[b * SEQ + s] - row[s] * 10.f;
                r = fmaxf(r, 0.f);
                g_res[b * SEQ + s] = r;
                loc += r;
                float v = r * g_m[b * SEQ + s];
                g_v2[b * SEQ + s] = v * v;
            }
            for (int o = 16; o; o >>= 1) loc += __shfl_xor_sync(~0u, loc, o);
            if (lane == 0) rsum[wid] = loc;
            __syncthreads();
            if (tid == 0) {
                float t = 0.f;
#pragma unroll
                for (int i = 0; i < 8; ++i) t += rsum[i];
                if (t * (1.f / SEQ) < 0.05f) g_done[b] = 1;
            }
        }
        target += NBLK; gbar(target);

        // ---- uniform early exit ----
        if (tid == 0) {
            int ad = 1;
#pragma unroll
            for (int i = 0; i < 8; ++i) ad &= g_done[i];
            s_brk = ad;
        }
        __syncthreads();
        if (s_brk) break;
        __syncthreads();
    }

    // ---- rescale selected rows x10 (all readers passed the last barrier) ----
    for (int p = g; p < PP; p += 32) {
        if (g_sel[b * PP + p]) {
            float4* wp = (float4*)(out + ((size_t)(b * PP + p)) * SEQ);
#pragma unroll
            for (int j = 0; j < 4; ++j) {
                int k = tid + 256 * j;
                float4 x = wp[k];
                x.x *= 10.f; x.y *= 10.f; x.z *= 10.f; x.w *= 10.f;
                wp[k] = x;
            }
        }
    }
}

// ---------------- launch --------------------------------------------------
extern "C" void kernel_launch(void* const* d_in, const int* in_sizes, int n_in,
                              void* d_out, int out_size)
{
    const float* x0     = (const float*)d_in[0];
    const float* fc1_w  = (const float*)d_in[1];
    const float* fc1_b  = (const float*)d_in[2];
    const float* ln1_g  = (const float*)d_in[3];
    const float* ln1_b  = (const float*)d_in[4];
    const float* fc2_w  = (const float*)d_in[5];
    const float* fc2_b  = (const float*)d_in[6];
    const float* ln2_g  = (const float*)d_in[7];
    const float* ln2_b  = (const float*)d_in[8];
    const float* c1w    = (const float*)d_in[9];
    const float* c1b    = (const float*)d_in[10];
    const float* c2w    = (const float*)d_in[11];
    const float* c2b    = (const float*)d_in[12];
    float* out = (float*)d_out;

    const int smemB = SM_TOTAL_F * (int)sizeof(float);
    cudaFuncSetAttribute(kernelB, cudaFuncAttributeMaxDynamicSharedMemorySize, smemB);

    prep_kernel<<<(PP * QPAD + 255) / 256, 256>>>(fc2_w, c1w, c1b, c2w, c2b);
    kernelB<<<NSAMP / BM, 256, smemB>>>(x0, fc1_w, fc1_b, ln1_g, ln1_b,
                                        fc2_b, ln2_g, ln2_b, out);
    select_persistent<<<NBLK, 256>>>(out);
}

// round 5
// speedup vs baseline: 1.4859x; 1.1266x over previous
#include <cuda_runtime.h>
#include <math.h>

// Problem constants
#define BATCH 8
#define SEQ   4096
#define PP    400          // 20x20
#define QPAD  416          // N padded to 16x26 for f32x2 pairs
#define NSAMP (BATCH*SEQ)  // 32768
#define ITERS 12           // max selection iterations (early-exit inside kernel)
#define NBLK  256          // persistent selection grid (must be co-resident)

typedef unsigned long long u64;

__device__ __forceinline__ u64 pack2(float lo, float hi) {
    u64 r; asm("mov.b64 %0,{%1,%2};" : "=l"(r) : "f"(lo), "f"(hi)); return r;
}
__device__ __forceinline__ void fma2(u64& d, u64 a, u64 b) {
    asm("fma.rn.f32x2 %0,%1,%2,%0;" : "+l"(d) : "l"(a), "l"(b));
}

// ---------------- scratch (static __device__, no allocations) ----------------
__device__ float g_m[NSAMP];            // mean over D of x0
__device__ float g_wT[PP * QPAD];       // fc2_w transposed + N-padded: [k][q]
__device__ float g_keff[25];            // composed 5x5 circular kernel
__device__ float g_c;                   // composed bias (after channel mean)
__device__ float g_act[BATCH * PP];     // per-iteration activities
__device__ int   g_sel[BATCH * PP];     // selection mask
__device__ int   g_done[BATCH];         // per-batch early-exit flag
__device__ float g_res[BATCH * SEQ];    // residual
__device__ float g_v2[BATCH * SEQ];     // (res*m)^2
__device__ unsigned g_bar;              // grid barrier counter (reset by prep)

// ---------------- prep: transpose+pad fc2_w, compose conv1*conv2 -------------
__global__ void prep_kernel(const float* __restrict__ fc2_w,
                            const float* __restrict__ c1w, const float* __restrict__ c1b,
                            const float* __restrict__ c2w, const float* __restrict__ c2b)
{
    int idx = blockIdx.x * 256 + threadIdx.x;
    if (idx < PP * QPAD) {
        int k = idx / QPAD, q = idx % QPAD;
        g_wT[idx] = (q < PP) ? fc2_w[q * PP + k] : 0.f;
    }
    if (blockIdx.x == 0 && threadIdx.x == 0) g_bar = 0u;   // reset grid barrier
    if (blockIdx.x == 0) {
        // stage weights in smem (coalesced), then 26 threads compose from smem
        __shared__ float s1w[45], s1b[5], s2w[450], s2b[10];
        int t = threadIdx.x;
        if (t < 45)  s1w[t] = c1w[t];
        if (t < 5)   s1b[t] = c1b[t];
        if (t < 256) { for (int i = t; i < 450; i += 256) s2w[i] = c2w[i]; }
        if (t < 10)  s2b[t] = c2b[t];
        __syncthreads();
        if (t < 25) {
            int u = t / 5, v = t % 5;
            float acc = 0.f;
            for (int oc = 0; oc < 10; ++oc)
                for (int ic = 0; ic < 5; ++ic)
#pragma unroll
                    for (int ay = 0; ay < 3; ++ay) {
                        int by = u - ay; if (by < 0 || by > 2) continue;
#pragma unroll
                        for (int ax = 0; ax < 3; ++ax) {
                            int bx = v - ax; if (bx < 0 || bx > 2) continue;
                            acc += s2w[((oc * 5 + ic) * 3 + by) * 3 + bx]
                                 * s1w[(ic * 3 + ay) * 3 + ax];
                        }
                    }
            g_keff[t] = acc * 0.1f;
        } else if (t == 25) {
            float acc = 0.f;
            for (int oc = 0; oc < 10; ++oc) {
                float t2 = s2b[oc];
                for (int ic = 0; ic < 5; ++ic) {
                    float sw = 0.f;
#pragma unroll
                    for (int bb = 0; bb < 9; ++bb) sw += s2w[(oc * 5 + ic) * 9 + bb];
                    t2 += s1b[ic] * sw;
                }
                acc += t2;
            }
            g_c = acc * 0.1f;
        }
    }
}

// ---- kernel B: fc1+ln1 (fused) + fc2 GEMM (f32x2) + ln2 + conv + sigmoid*0.1
#define BM 64
#define BK 16
#define AH_STRIDE 404
#define SM_AH (BM * AH_STRIDE)       // h1 tile [m][k], later reused as Cs [m][q]
#define SM_BS (BK * QPAD)            // 16 x 416
#define SM_TOTAL_F (SM_AH + SM_BS + 1200 + 6*PP + 26)
#define NB4 (BK * QPAD / 4)          // 1664 float4 per B tile
#define NPF ((NB4 + 255) / 256)      // 7 prefetch regs per thread

__global__ void __launch_bounds__(256, 1) kernelB(
    const float* __restrict__ x0,
    const float* __restrict__ fc1_w, const float* __restrict__ fc1_b,
    const float* __restrict__ ln1_g, const float* __restrict__ ln1_b,
    const float* __restrict__ fc2_b, const float* __restrict__ ln2_g,
    const float* __restrict__ ln2_b, float* __restrict__ out)
{
    extern __shared__ float sm[];
    float* Ah  = sm;                   // [64][404]: h1, then Cs
    float* Bs  = Ah + SM_AH;           // [16][416]
    float* fw  = Bs + SM_BS;           // fc1_w 400x3
    float* fb  = fw + 1200;
    float* l1g = fb + PP;
    float* l1b = l1g + PP;
    float* pb  = l1b + PP;             // fc2_b
    float* pg  = pb + PP;              // ln2_g
    float* pb2 = pg + PP;              // ln2_b
    float* ks  = pb2 + PP;             // keff[25] + c

    int tid = threadIdx.x;
    int lane = tid & 31, wid = tid >> 5;
    int s0 = blockIdx.x * BM;

    for (int i = tid; i < 1200; i += 256) fw[i] = fc1_w[i];
    for (int i = tid; i < PP; i += 256) {
        fb[i] = fc1_b[i]; l1g[i] = ln1_g[i]; l1b[i] = ln1_b[i];
        pb[i] = fc2_b[i]; pg[i] = ln2_g[i]; pb2[i] = ln2_b[i];
    }
    if (tid < 26) ks[tid] = (tid < 25) ? g_keff[tid] : g_c;
    __syncthreads();

    // ---- fused fc1 + relu + ln1 into Ah (one warp per sample, 8 rounds) ----
    for (int r = wid; r < BM; r += 8) {
        int ss = s0 + r;
        const float* xp = x0 + (size_t)ss * 3;
        float xa = xp[0], xb = xp[1], xc = xp[2];
        if (lane == 0) g_m[ss] = (xa + xb + xc) * (1.f / 3.f);
        float v[13];
        float sum = 0.f, sq = 0.f;
#pragma unroll
        for (int k = 0; k < 13; ++k) {
            int q = lane + 32 * k;
            float h = 0.f;
            if (q < PP) {
                h = xa * fw[q * 3] + xb * fw[q * 3 + 1] + xc * fw[q * 3 + 2] + fb[q];
                h = fmaxf(h, 0.f);
            }
            v[k] = h; sum += h; sq += h * h;
        }
        for (int o = 16; o; o >>= 1) {
            sum += __shfl_xor_sync(~0u, sum, o);
            sq  += __shfl_xor_sync(~0u, sq, o);
        }
        float mu = sum * (1.f / PP);
        float var = sq * (1.f / PP) - mu * mu;
        float rs = rsqrtf(var + 1e-5f);
#pragma unroll
        for (int k = 0; k < 13; ++k) {
            int q = lane + 32 * k;
            if (q < PP) Ah[r * AH_STRIDE + q] = (v[k] - mu) * rs * l1g[q] + l1b[q];
        }
    }

    // ---- fc2 GEMM mainloop (f32x2), A resident, B software-pipelined ----
    int tr = tid >> 4, tc = tid & 15;     // 4 M-rows x 26 N-cols per thread
    u64 acc[4][13];
#pragma unroll
    for (int i = 0; i < 4; ++i)
#pragma unroll
        for (int j = 0; j < 13; ++j) acc[i][j] = 0ull;

    float4 pre[NPF];
    {   // prefetch first B tile
#pragma unroll
        for (int c = 0; c < NPF; ++c) {
            int f = tid + c * 256;
            if (f < NB4) pre[c] = *(const float4*)(g_wT + 4 * f);
        }
    }

    for (int kk = 0; kk < PP; kk += BK) {
        __syncthreads();   // Bs consumers of previous tile done (and Ah ready at kk=0)
#pragma unroll
        for (int c = 0; c < NPF; ++c) {
            int f = tid + c * 256;
            if (f < NB4) *(float4*)(Bs + 4 * f) = pre[c];
        }
        __syncthreads();
        if (kk + BK < PP) {   // prefetch next tile; LDGs overlap compute below
#pragma unroll
            for (int c = 0; c < NPF; ++c) {
                int f = tid + c * 256;
                if (f < NB4) pre[c] = *(const float4*)(g_wT + (size_t)(kk + BK) * QPAD + 4 * f);
            }
        }
#pragma unroll
        for (int k = 0; k < BK; ++k) {
            u64 ap[4], bv[13];
#pragma unroll
            for (int i = 0; i < 4; ++i) {
                float av = Ah[(tr * 4 + i) * AH_STRIDE + kk + k];
                ap[i] = pack2(av, av);
            }
#pragma unroll
            for (int j = 0; j < 13; ++j)
                bv[j] = *(const u64*)(Bs + k * QPAD + tc * 26 + 2 * j);
#pragma unroll
            for (int i = 0; i < 4; ++i)
#pragma unroll
                for (int j = 0; j < 13; ++j) fma2(acc[i][j], ap[i], bv[j]);
        }
    }
    __syncthreads();

    // ---- bias + relu -> Cs (overlay Ah) ----
    float* Cs = Ah;
#pragma unroll
    for (int i = 0; i < 4; ++i)
#pragma unroll
        for (int j = 0; j < 13; ++j) {
            float2 v = *(float2*)&acc[i][j];
            int q0 = tc * 26 + 2 * j;
            int row = (tr * 4 + i) * AH_STRIDE;
            if (q0 < PP)     Cs[row + q0]     = fmaxf(v.x + pb[q0], 0.f);
            if (q0 + 1 < PP) Cs[row + q0 + 1] = fmaxf(v.y + pb[q0 + 1], 0.f);
        }
    __syncthreads();

    // ---- LN2 per sample row (8 warps x 8 rows) ----
    for (int r = wid * 8; r < wid * 8 + 8; ++r) {
        float sum = 0.f, sq = 0.f;
#pragma unroll
        for (int k = 0; k < 13; ++k) {
            int q = lane + 32 * k;
            if (q < PP) { float x = Cs[r * AH_STRIDE + q]; sum += x; sq += x * x; }
        }
        for (int o = 16; o; o >>= 1) {
            sum += __shfl_xor_sync(~0u, sum, o);
            sq  += __shfl_xor_sync(~0u, sq, o);
        }
        float mu = sum * (1.f / PP);
        float var = sq * (1.f / PP) - mu * mu;
        float rs = rsqrtf(var + 1e-5f);
#pragma unroll
        for (int k = 0; k < 13; ++k) {
            int q = lane + 32 * k;
            if (q < PP) {
                float x = Cs[r * AH_STRIDE + q];
                Cs[r * AH_STRIDE + q] = (x - mu) * rs * pg[q] + pb2[q];
            }
        }
    }
    __syncthreads();

    // ---- 5x5 circular conv + 0.1*sigmoid + transposed write ----
    // work item = (pg, r8g): pg = 100 groups of 4 adjacent jj; r8g = 8 groups of 8 rows
    int b = s0 >> 12;          // SEQ=4096
    int sw = s0 & (SEQ - 1);
    float kreg[25];
#pragma unroll
    for (int d = 0; d < 25; ++d) kreg[d] = ks[d];
    float cc = ks[25];

    for (int item = tid; item < 800; item += 256) {
        int r8 = (item & 7) * 8;           // sample row group
        int pg = item >> 3;                // 0..99
        int ii = pg / 5, jj0 = (pg % 5) * 4;
        int wy[5], wx[8];
#pragma unroll
        for (int dy = 0; dy < 5; ++dy) wy[dy] = ((ii + dy - 2 + 20) % 20) * 20;
#pragma unroll
        for (int dx = 0; dx < 8; ++dx) wx[dx] = (jj0 + dx - 2 + 20) % 20;

        float o[4][8];
#pragma unroll
        for (int rr = 0; rr < 8; ++rr) {
            const float* crow = Cs + (r8 + rr) * AH_STRIDE;
            float patch[5][8];
#pragma unroll
            for (int dy = 0; dy < 5; ++dy)
#pragma unroll
                for (int dx = 0; dx < 8; ++dx)
                    patch[dy][dx] = crow[wy[dy] + wx[dx]];
#pragma unroll
            for (int t = 0; t < 4; ++t) {
                float a = cc;
#pragma unroll
                for (int du = 0; du < 5; ++du)
#pragma unroll
                    for (int dv = 0; dv < 5; ++dv)
                        a += kreg[du * 5 + dv] * patch[du][t + dv];
                o[t][rr] = 0.1f / (1.f + __expf(-a));
            }
        }
#pragma unroll
        for (int t = 0; t < 4; ++t) {
            int p = ii * 20 + jj0 + t;
            float* obase = out + ((size_t)(b * PP + p)) * SEQ + sw + r8;
            *(float4*)(obase)     = make_float4(o[t][0], o[t][1], o[t][2], o[t][3]);
            *(float4*)(obase + 4) = make_float4(o[t][4], o[t][5], o[t][6], o[t][7]);
        }
    }
}

// ---------------- persistent selection: one launch, grid barriers -----------
__device__ __forceinline__ void gbar(unsigned& target)
{
    __syncthreads();
    __threadfence();                        // flush writes (gpu scope)
    if (threadIdx.x == 0) {
        atomicAdd(&g_bar, 1u);
        while (*(volatile unsigned*)&g_bar < target) { }
    }
    __syncthreads();
    __threadfence();                        // invalidate L1D for fresh reads
}

__global__ void __launch_bounds__(256) select_persistent(float* __restrict__ out)
{
    int b = blockIdx.x & 7;        // batch
    int g = blockIdx.x >> 3;       // 0..31 within batch
    int tid = threadIdx.x, lane = tid & 31, wid = tid >> 5;
    unsigned target = 0;
    __shared__ float ws[8];
    __shared__ float wvv[8];
    __shared__ int   wii[8];
    __shared__ float rsum[8];
    __shared__ int   s_pid, s_brk;

    // ---- init slices ----
    if (g < 16) {
        int s = g * 256 + tid;     // covers 4096
        float m = g_m[b * SEQ + s];
        g_res[b * SEQ + s] = 1.f;
        g_v2[b * SEQ + s] = m * m;
    } else if (g == 16 || g == 17) {
        int p = (g - 16) * 256 + tid;
        if (p < PP) g_sel[b * PP + p] = 0;
    } else if (g == 18 && tid == 0) {
        g_done[b] = 0;
    }
    target += NBLK; gbar(target);

    for (int it = 0; it < ITERS; ++it) {
        // ---- activity phase: 32 blocks x ~13 rows each ----
        if (!g_done[b]) {
            const float4* vv = (const float4*)(g_v2 + (size_t)b * SEQ);
            for (int p = g; p < PP; p += 32) {
                if (g_sel[b * PP + p]) {
                    if (tid == 0) g_act[b * PP + p] = -1.f;
                    continue;
                }
                const float4* wp = (const float4*)(out + ((size_t)(b * PP + p)) * SEQ);
                float a = 0.f;
#pragma unroll
                for (int j = 0; j < 4; ++j) {
                    int k = tid + 256 * j;
                    float4 x = wp[k]; float4 y = vv[k];
                    a += x.x * x.x * y.x + x.y * x.y * y.y
                       + x.z * x.z * y.z + x.w * x.w * y.w;
                }
                for (int o = 16; o; o >>= 1) a += __shfl_xor_sync(~0u, a, o);
                if (lane == 0) ws[wid] = a;
                __syncthreads();
                if (tid == 0) {
                    float t = 0.f;
#pragma unroll
                    for (int i = 0; i < 8; ++i) t += ws[i];
                    g_act[b * PP + p] = t;
                }
                __syncthreads();
            }
        }
        target += NBLK; gbar(target);

        // ---- update phase: leader block per batch ----
        if (g == 0 && !g_done[b]) {
            float bv = -2.f; int bi = 0x7fffffff;
            for (int p = tid; p < PP; p += 256) {
                float v = g_act[b * PP + p];
                if (v > bv || (v == bv && p < bi)) { bv = v; bi = p; }
            }
            for (int o = 16; o; o >>= 1) {
                float ov = __shfl_xor_sync(~0u, bv, o);
                int   oi = __shfl_xor_sync(~0u, bi, o);
                if (ov > bv || (ov == bv && oi < bi)) { bv = ov; bi = oi; }
            }
            if (lane == 0) { wvv[wid] = bv; wii[wid] = bi; }
            __syncthreads();
            if (tid == 0) {
                float fv = -2.f; int fi = 0x7fffffff;
#pragma unroll
                for (int i = 0; i < 8; ++i)
                    if (wvv[i] > fv || (wvv[i] == fv && wii[i] < fi)) { fv = wvv[i]; fi = wii[i]; }
                s_pid = fi; g_sel[b * PP + fi] = 1;
            }
            __syncthreads();
            int pid = s_pid;

            const float* row = out + ((size_t)(b * PP + pid)) * SEQ;  // 0.1*w
            float loc = 0.f;
            for (int s = tid; s < SEQ; s += 256) {
                float r = g_res[b * SEQ + s] - row[s] * 10.f;
                r = fmaxf(r, 0.f);
                g_res[b * SEQ + s] = r;
                loc += r;
                float v = r * g_m[b * SEQ + s];
                g_v2[b * SEQ + s] = v * v;
            }
            for (int o = 16; o; o >>= 1) loc += __shfl_xor_sync(~0u, loc, o);
            if (lane == 0) rsum[wid] = loc;
            __syncthreads();
            if (tid == 0) {
                float t = 0.f;
#pragma unroll
                for (int i = 0; i < 8; ++i) t += rsum[i];
                if (t * (1.f / SEQ) < 0.05f) g_done[b] = 1;
            }
        }
        target += NBLK; gbar(target);

        // ---- uniform early exit ----
        if (tid == 0) {
            int ad = 1;
#pragma unroll
            for (int i = 0; i < 8; ++i) ad &= g_done[i];
            s_brk = ad;
        }
        __syncthreads();
        if (s_brk) break;
        __syncthreads();
    }

    // ---- rescale selected rows x10 (all readers passed the last barrier) ----
    for (int p = g; p < PP; p += 32) {
        if (g_sel[b * PP + p]) {
            float4* wp = (float4*)(out + ((size_t)(b * PP + p)) * SEQ);
#pragma unroll
            for (int j = 0; j < 4; ++j) {
                int k = tid + 256 * j;
                float4 x = wp[k];
                x.x *= 10.f; x.y *= 10.f; x.z *= 10.f; x.w *= 10.f;
                wp[k] = x;
            }
        }
    }
}

// ---------------- launch --------------------------------------------------
extern "C" void kernel_launch(void* const* d_in, const int* in_sizes, int n_in,
                              void* d_out, int out_size)
{
    const float* x0     = (const float*)d_in[0];
    const float* fc1_w  = (const float*)d_in[1];
    const float* fc1_b  = (const float*)d_in[2];
    const float* ln1_g  = (const float*)d_in[3];
    const float* ln1_b  = (const float*)d_in[4];
    const float* fc2_w  = (const float*)d_in[5];
    const float* fc2_b  = (const float*)d_in[6];
    const float* ln2_g  = (const float*)d_in[7];
    const float* ln2_b  = (const float*)d_in[8];
    const float* c1w    = (const float*)d_in[9];
    const float* c1b    = (const float*)d_in[10];
    const float* c2w    = (const float*)d_in[11];
    const float* c2b    = (const float*)d_in[12];
    float* out = (float*)d_out;

    const int smemB = SM_TOTAL_F * (int)sizeof(float);
    cudaFuncSetAttribute(kernelB, cudaFuncAttributeMaxDynamicSharedMemorySize, smemB);

    prep_kernel<<<(PP * QPAD + 255) / 256, 256>>>(fc2_w, c1w, c1b, c2w, c2b);
    kernelB<<<NSAMP / BM, 256, smemB>>>(x0, fc1_w, fc1_b, ln1_g, ln1_b,
                                        fc2_b, ln2_g, ln2_b, out);
    select_persistent<<<NBLK, 256>>>(out);
}

// round 8
// speedup vs baseline: 2.1038x; 1.4158x over previous
#include <cuda_runtime.h>
#include <cuda_bf16.h>
#include <math.h>
#include <stdint.h>

// Problem constants
#define BATCH 8
#define SEQ   4096
#define PP    400           // 20x20
#define NSAMP (BATCH*SEQ)   // 32768
#define ITERS 12
#define NBLK  256           // persistent selection grid

// GEMM: M=32768 (64/CTA), N=416 (52 n8-tiles), K=400 (25 k16-steps)
#define NK16  25
#define NNT   52

typedef unsigned long long u64;

// ---------------- scratch (static __device__, no allocations) ----------------
__device__ unsigned g_Bfrag[NK16 * NNT * 2 * 64];  // [k16][nt][plane][lane][2] u32
__device__ float  g_m[NSAMP];
__device__ float  g_keff[25];
__device__ float  g_c;
__device__ float  g_act[BATCH * PP];
__device__ int    g_sel[BATCH * PP];
__device__ int    g_done[BATCH];
__device__ float  g_res[BATCH * SEQ];
__device__ float  g_v2[BATCH * SEQ];
__device__ unsigned g_bar;

// ---------------- helpers ----------------
__device__ __forceinline__ void bsplit(float lo, float hi, uint32_t& h, uint32_t& l)
{
    asm("cvt.rn.bf16x2.f32 %0,%1,%2;" : "=r"(h) : "f"(hi), "f"(lo));
    float hlo = __uint_as_float(h << 16);
    float hhi = __uint_as_float(h & 0xffff0000u);
    asm("cvt.rn.bf16x2.f32 %0,%1,%2;" : "=r"(l) : "f"(hi - hhi), "f"(lo - hlo));
}
__device__ __forceinline__ void mma16816(float* c, const uint32_t* a,
                                         uint32_t b0, uint32_t b1)
{
    asm volatile(
        "mma.sync.aligned.m16n8k16.row.col.f32.bf16.bf16.f32 "
        "{%0,%1,%2,%3},{%4,%5,%6,%7},{%8,%9},{%0,%1,%2,%3};"
        : "+f"(c[0]), "+f"(c[1]), "+f"(c[2]), "+f"(c[3])
        : "r"(a[0]), "r"(a[1]), "r"(a[2]), "r"(a[3]), "r"(b0), "r"(b1));
}

// ---------------- prep: B fragment planes + conv compose + barrier reset -----
__global__ void prep_kernel(const float* __restrict__ fc2_w,
                            const float* __restrict__ c1w, const float* __restrict__ c1b,
                            const float* __restrict__ c2w, const float* __restrict__ c2b)
{
    if (blockIdx.x < 650) {
        int e = blockIdx.x * 256 + threadIdx.x;   // [k16][nt][plane][lane][reg]
        int reg   = e & 1;
        int lane  = (e >> 1) & 31;
        int plane = (e >> 6) & 1;
        int r     = e >> 7;                        // 0..1299
        int nt  = r % NNT;
        int k16 = r / NNT;
        int g = lane >> 2, tg = lane & 3;
        int n  = nt * 8 + g;
        int kr = k16 * 16 + tg * 2 + reg * 8;
        float v0 = (n < PP) ? fc2_w[n * PP + kr] : 0.f;
        float v1 = (n < PP) ? fc2_w[n * PP + kr + 1] : 0.f;
        uint32_t h, l;
        bsplit(v0, v1, h, l);                      // lo half = k row kr, hi = kr+1
        g_Bfrag[(((size_t)r * 2 + plane) * 32 + lane) * 2 + reg] = plane ? l : h;
        return;
    }
    // last block: keff compose + g_bar reset
    __shared__ float s1w[45], s1b[5], s2w[450], s2b[10], part[250];
    int t = threadIdx.x;
    if (t == 0) g_bar = 0u;
    if (t < 45)  s1w[t] = c1w[t];
    if (t < 5)   s1b[t] = c1b[t];
    for (int i = t; i < 450; i += 256) s2w[i] = c2w[i];
    if (t < 10)  s2b[t] = c2b[t];
    __syncthreads();
    if (t < 250) {
        int uv = t / 10, oc = t % 10;
        int u = uv / 5, v = uv % 5;
        float acc = 0.f;
        for (int ic = 0; ic < 5; ++ic)
#pragma unroll
            for (int ay = 0; ay < 3; ++ay) {
                int by = u - ay; if (by < 0 || by > 2) continue;
#pragma unroll
                for (int ax = 0; ax < 3; ++ax) {
                    int bx = v - ax; if (bx < 0 || bx > 2) continue;
                    acc += s2w[((oc * 5 + ic) * 3 + by) * 3 + bx] * s1w[(ic * 3 + ay) * 3 + ax];
                }
            }
        part[t] = acc;
    }
    __syncthreads();
    if (t < 25) {
        float acc = 0.f;
#pragma unroll
        for (int oc = 0; oc < 10; ++oc) acc += part[t * 10 + oc];
        g_keff[t] = acc * 0.1f;
    } else if (t == 25) {
        float acc = 0.f;
        for (int oc = 0; oc < 10; ++oc) {
            float t2 = s2b[oc];
            for (int ic = 0; ic < 5; ++ic) {
                float sw = 0.f;
#pragma unroll
                for (int bb = 0; bb < 9; ++bb) sw += s2w[(oc * 5 + ic) * 9 + bb];
                t2 += s1b[ic] * sw;
            }
            acc += t2;
        }
        g_c = acc * 0.1f;
    }
}

// ---- kernel B: fc1+ln1 + mma.sync bf16-split GEMM + ln2 + conv + 0.1*sigmoid
#define BM 64
#define AH_STRIDE 404
#define REGION (BM * AH_STRIDE)        // fp32 h1 tile, later reused as Cs
// float-index param offsets
#define P_FW   (REGION)                // 1200
#define P_FB   (P_FW + 1200)
#define P_L1G  (P_FB + PP)
#define P_L1B  (P_L1G + PP)
#define P_PB   (P_L1B + PP)
#define P_PG   (P_PB + PP)
#define P_PB2  (P_PG + PP)
#define P_KS   (P_PB2 + PP)            // 26
#define SMEM_TOTAL ((P_KS + 32) * 4)

__global__ void __launch_bounds__(256, 1) kernelB(
    const float* __restrict__ x0,
    const float* __restrict__ fc1_w, const float* __restrict__ fc1_b,
    const float* __restrict__ ln1_g, const float* __restrict__ ln1_b,
    const float* __restrict__ fc2_b, const float* __restrict__ ln2_g,
    const float* __restrict__ ln2_b, float* __restrict__ out)
{
    extern __shared__ float smf[];
    float* Ah = smf;                   // [64][404], fp32; overlaid by Cs later

    int tid = threadIdx.x, lane = tid & 31, wid = tid >> 5;
    int s0 = blockIdx.x * BM;

    for (int i = tid; i < 1200; i += 256) smf[P_FW + i] = fc1_w[i];
    for (int i = tid; i < PP; i += 256) {
        smf[P_FB + i] = fc1_b[i]; smf[P_L1G + i] = ln1_g[i]; smf[P_L1B + i] = ln1_b[i];
        smf[P_PB + i] = fc2_b[i]; smf[P_PG + i] = ln2_g[i]; smf[P_PB2 + i] = ln2_b[i];
    }
    if (tid < 26) smf[P_KS + tid] = (tid < 25) ? g_keff[tid] : g_c;
    __syncthreads();

    // ---- fused fc1 + relu + ln1 into Ah (one warp per sample, 8 rounds) ----
    for (int r = wid; r < BM; r += 8) {
        int ss = s0 + r;
        const float* xp = x0 + (size_t)ss * 3;
        float xa = xp[0], xb = xp[1], xc = xp[2];
        if (lane == 0) g_m[ss] = (xa + xb + xc) * (1.f / 3.f);
        float v[13];
        float sum = 0.f, sq = 0.f;
#pragma unroll
        for (int k = 0; k < 13; ++k) {
            int q = lane + 32 * k;
            float h = 0.f;
            if (q < PP) {
                h = fmaxf(xa * smf[P_FW + q * 3] + xb * smf[P_FW + q * 3 + 1]
                        + xc * smf[P_FW + q * 3 + 2] + smf[P_FB + q], 0.f);
            }
            v[k] = h; sum += h; sq += h * h;
        }
        for (int o = 16; o; o >>= 1) {
            sum += __shfl_xor_sync(~0u, sum, o);
            sq  += __shfl_xor_sync(~0u, sq, o);
        }
        float mu = sum * (1.f / PP);
        float var = sq * (1.f / PP) - mu * mu;
        float rs = rsqrtf(var + 1e-5f);
#pragma unroll
        for (int k = 0; k < 13; ++k) {
            int q = lane + 32 * k;
            if (q < PP) Ah[r * AH_STRIDE + q] = (v[k] - mu) * rs * smf[P_L1G + q] + smf[P_L1B + q];
        }
    }
    __syncthreads();

    // ---- mma.sync bf16-split mainloop ----
    // 8 warps: wr = wid>>1 (m16 block, rows 16wr..), wc = wid&1 (26 n8-tiles each)
    int wr = wid >> 1, wc = wid & 1;
    int g = lane >> 2, tg = lane & 3;
    float acc[26][4];
#pragma unroll
    for (int j = 0; j < 26; ++j)
#pragma unroll
        for (int i = 0; i < 4; ++i) acc[j][i] = 0.f;

    const u64* bfr = (const u64*)g_Bfrag;
    int r0 = 16 * wr + g;
    const float* A0 = Ah + r0 * AH_STRIDE + 2 * tg;
    const float* A1 = Ah + (r0 + 8) * AH_STRIDE + 2 * tg;

    for (int k16 = 0; k16 < NK16; ++k16) {
        int kb = k16 * 16;
        float2 x0v = *(const float2*)(A0 + kb);
        float2 x1v = *(const float2*)(A1 + kb);
        float2 x2v = *(const float2*)(A0 + kb + 8);
        float2 x3v = *(const float2*)(A1 + kb + 8);
        uint32_t aH[4], aL[4];
        bsplit(x0v.x, x0v.y, aH[0], aL[0]);
        bsplit(x1v.x, x1v.y, aH[1], aL[1]);
        bsplit(x2v.x, x2v.y, aH[2], aL[2]);
        bsplit(x3v.x, x3v.y, aH[3], aL[3]);

        // u64 layout: index = r*64 + plane*32 + lane, where r = k16*NNT + nt
        size_t base = ((size_t)(k16 * NNT + wc * 26)) * 64 + lane;
#pragma unroll
        for (int j = 0; j < 26; ++j) {
            u64 w0 = bfr[base + (size_t)j * 64];        // plane 0 (hi)
            u64 w1 = bfr[base + (size_t)j * 64 + 32];   // plane 1 (residual)
            uint32_t bH0 = (uint32_t)w0, bH1 = (uint32_t)(w0 >> 32);
            uint32_t bL0 = (uint32_t)w1, bL1 = (uint32_t)(w1 >> 32);
            mma16816(acc[j], aH, bH0, bH1);
            mma16816(acc[j], aH, bL0, bL1);
            mma16816(acc[j], aL, bH0, bH1);
        }
    }
    __syncthreads();   // all mainloop reads of Ah done -> safe to overlay Cs

    // ---- bias + relu -> Cs (overlay Ah) ----
    float* Cs = Ah;
#pragma unroll
    for (int j = 0; j < 26; ++j) {
        int n0 = (wc * 26 + j) * 8;
        int q0 = n0 + 2 * tg;
        int rowa = (16 * wr + g) * AH_STRIDE;
        int rowb = (16 * wr + g + 8) * AH_STRIDE;
        if (q0 < PP) {
            Cs[rowa + q0] = fmaxf(acc[j][0] + smf[P_PB + q0], 0.f);
            Cs[rowb + q0] = fmaxf(acc[j][2] + smf[P_PB + q0], 0.f);
        }
        if (q0 + 1 < PP) {
            Cs[rowa + q0 + 1] = fmaxf(acc[j][1] + smf[P_PB + q0 + 1], 0.f);
            Cs[rowb + q0 + 1] = fmaxf(acc[j][3] + smf[P_PB + q0 + 1], 0.f);
        }
    }
    __syncthreads();

    // ---- LN2 per sample row (8 warps x 8 rows) ----
    for (int r = wid * 8; r < wid * 8 + 8; ++r) {
        float sum = 0.f, sq = 0.f;
#pragma unroll
        for (int k = 0; k < 13; ++k) {
            int q = lane + 32 * k;
            if (q < PP) { float x = Cs[r * AH_STRIDE + q]; sum += x; sq += x * x; }
        }
        for (int o = 16; o; o >>= 1) {
            sum += __shfl_xor_sync(~0u, sum, o);
            sq  += __shfl_xor_sync(~0u, sq, o);
        }
        float mu = sum * (1.f / PP);
        float var = sq * (1.f / PP) - mu * mu;
        float rs = rsqrtf(var + 1e-5f);
#pragma unroll
        for (int k = 0; k < 13; ++k) {
            int q = lane + 32 * k;
            if (q < PP) {
                float x = Cs[r * AH_STRIDE + q];
                Cs[r * AH_STRIDE + q] = (x - mu) * rs * smf[P_PG + q] + smf[P_PB2 + q];
            }
        }
    }
    __syncthreads();

    // ---- 5x5 circular conv + 0.1*sigmoid + transposed write ----
    int b = s0 >> 12;
    int sw0 = s0 & (SEQ - 1);
    float kreg[25];
#pragma unroll
    for (int d = 0; d < 25; ++d) kreg[d] = smf[P_KS + d];
    float cc0 = smf[P_KS + 25];

    for (int item = tid; item < 800; item += 256) {
        int r8 = (item & 7) * 8;
        int pgi = item >> 3;
        int ii = pgi / 5, jj0 = (pgi % 5) * 4;
        int wy[5], wx[8];
#pragma unroll
        for (int dy = 0; dy < 5; ++dy) wy[dy] = ((ii + dy - 2 + 20) % 20) * 20;
#pragma unroll
        for (int dx = 0; dx < 8; ++dx) wx[dx] = (jj0 + dx - 2 + 20) % 20;

        float o[4][8];
#pragma unroll
        for (int rr = 0; rr < 8; ++rr) {
            const float* crow = Cs + (r8 + rr) * AH_STRIDE;
            float patch[5][8];
#pragma unroll
            for (int dy = 0; dy < 5; ++dy)
#pragma unroll
                for (int dx = 0; dx < 8; ++dx)
                    patch[dy][dx] = crow[wy[dy] + wx[dx]];
#pragma unroll
            for (int t = 0; t < 4; ++t) {
                float a = cc0;
#pragma unroll
                for (int du = 0; du < 5; ++du)
#pragma unroll
                    for (int dv = 0; dv < 5; ++dv)
                        a += kreg[du * 5 + dv] * patch[du][t + dv];
                o[t][rr] = 0.1f / (1.f + __expf(-a));
            }
        }
#pragma unroll
        for (int t = 0; t < 4; ++t) {
            int p = ii * 20 + jj0 + t;
            float* obase = out + ((size_t)(b * PP + p)) * SEQ + sw0 + r8;
            *(float4*)(obase)     = make_float4(o[t][0], o[t][1], o[t][2], o[t][3]);
            *(float4*)(obase + 4) = make_float4(o[t][4], o[t][5], o[t][6], o[t][7]);
        }
    }
}

// ---------------- persistent selection (unchanged, proven) ------------------
__device__ __forceinline__ void gbar(unsigned& target)
{
    __syncthreads();
    __threadfence();
    if (threadIdx.x == 0) {
        atomicAdd(&g_bar, 1u);
        while (*(volatile unsigned*)&g_bar < target) { }
    }
    __syncthreads();
    __threadfence();
}

__global__ void __launch_bounds__(256) select_persistent(float* __restrict__ out)
{
    int b = blockIdx.x & 7;
    int g = blockIdx.x >> 3;
    int tid = threadIdx.x, lane = tid & 31, wid = tid >> 5;
    unsigned target = 0;
    __shared__ float ws[8];
    __shared__ float wvv[8];
    __shared__ int   wii[8];
    __shared__ float rsum[8];
    __shared__ int   s_pid, s_brk;

    if (g < 16) {
        int s = g * 256 + tid;
        float m = g_m[b * SEQ + s];
        g_res[b * SEQ + s] = 1.f;
        g_v2[b * SEQ + s] = m * m;
    } else if (g == 16 || g == 17) {
        int p = (g - 16) * 256 + tid;
        if (p < PP) g_sel[b * PP + p] = 0;
    } else if (g == 18 && tid == 0) {
        g_done[b] = 0;
    }
    target += NBLK; gbar(target);

    for (int it = 0; it < ITERS; ++it) {
        if (!g_done[b]) {
            const float4* vv = (const float4*)(g_v2 + (size_t)b * SEQ);
            for (int p = g; p < PP; p += 32) {
                if (g_sel[b * PP + p]) {
                    if (tid == 0) g_act[b * PP + p] = -1.f;
                    continue;
                }
                const float4* wp = (const float4*)(out + ((size_t)(b * PP + p)) * SEQ);
                float a = 0.f;
#pragma unroll
                for (int j = 0; j < 4; ++j) {
                    int k = tid + 256 * j;
                    float4 x = wp[k]; float4 y = vv[k];
                    a += x.x * x.x * y.x + x.y * x.y * y.y
                       + x.z * x.z * y.z + x.w * x.w * y.w;
                }
                for (int o = 16; o; o >>= 1) a += __shfl_xor_sync(~0u, a, o);
                if (lane == 0) ws[wid] = a;
                __syncthreads();
                if (tid == 0) {
                    float t = 0.f;
#pragma unroll
                    for (int i = 0; i < 8; ++i) t += ws[i];
                    g_act[b * PP + p] = t;
                }
                __syncthreads();
            }
        }
        target += NBLK; gbar(target);

        if (g == 0 && !g_done[b]) {
            float bv = -2.f; int bi = 0x7fffffff;
            for (int p = tid; p < PP; p += 256) {
                float v = g_act[b * PP + p];
                if (v > bv || (v == bv && p < bi)) { bv = v; bi = p; }
            }
            for (int o = 16; o; o >>= 1) {
                float ov = __shfl_xor_sync(~0u, bv, o);
                int   oi = __shfl_xor_sync(~0u, bi, o);
                if (ov > bv || (ov == bv && oi < bi)) { bv = ov; bi = oi; }
            }
            if (lane == 0) { wvv[wid] = bv; wii[wid] = bi; }
            __syncthreads();
            if (tid == 0) {
                float fv = -2.f; int fi = 0x7fffffff;
#pragma unroll
                for (int i = 0; i < 8; ++i)
                    if (wvv[i] > fv || (wvv[i] == fv && wii[i] < fi)) { fv = wvv[i]; fi = wii[i]; }
                s_pid = fi; g_sel[b * PP + fi] = 1;
            }
            __syncthreads();
            int pid = s_pid;

            const float* row = out + ((size_t)(b * PP + pid)) * SEQ;
            float loc = 0.f;
            for (int s = tid; s < SEQ; s += 256) {
                float r = g_res[b * SEQ + s] - row[s] * 10.f;
                r = fmaxf(r, 0.f);
                g_res[b * SEQ + s] = r;
                loc += r;
                float v = r * g_m[b * SEQ + s];
                g_v2[b * SEQ + s] = v * v;
            }
            for (int o = 16; o; o >>= 1) loc += __shfl_xor_sync(~0u, loc, o);
            if (lane == 0) rsum[wid] = loc;
            __syncthreads();
            if (tid == 0) {
                float t = 0.f;
#pragma unroll
                for (int i = 0; i < 8; ++i) t += rsum[i];
                if (t * (1.f / SEQ) < 0.05f) g_done[b] = 1;
            }
        }
        target += NBLK; gbar(target);

        if (tid == 0) {
            int ad = 1;
#pragma unroll
            for (int i = 0; i < 8; ++i) ad &= g_done[i];
            s_brk = ad;
        }
        __syncthreads();
        if (s_brk) break;
        __syncthreads();
    }

    for (int p = g; p < PP; p += 32) {
        if (g_sel[b * PP + p]) {
            float4* wp = (float4*)(out + ((size_t)(b * PP + p)) * SEQ);
#pragma unroll
            for (int j = 0; j < 4; ++j) {
                int k = tid + 256 * j;
                float4 x = wp[k];
                x.x *= 10.f; x.y *= 10.f; x.z *= 10.f; x.w *= 10.f;
                wp[k] = x;
            }
        }
    }
}

// ---------------- launch --------------------------------------------------
extern "C" void kernel_launch(void* const* d_in, const int* in_sizes, int n_in,
                              void* d_out, int out_size)
{
    const float* x0     = (const float*)d_in[0];
    const float* fc1_w  = (const float*)d_in[1];
    const float* fc1_b  = (const float*)d_in[2];
    const float* ln1_g  = (const float*)d_in[3];
    const float* ln1_b  = (const float*)d_in[4];
    const float* fc2_w  = (const float*)d_in[5];
    const float* fc2_b  = (const float*)d_in[6];
    const float* ln2_g  = (const float*)d_in[7];
    const float* ln2_b  = (const float*)d_in[8];
    const float* c1w    = (const float*)d_in[9];
    const float* c1b    = (const float*)d_in[10];
    const float* c2w    = (const float*)d_in[11];
    const float* c2b    = (const float*)d_in[12];
    float* out = (float*)d_out;

    cudaFuncSetAttribute(kernelB, cudaFuncAttributeMaxDynamicSharedMemorySize, SMEM_TOTAL);

    prep_kernel<<<651, 256>>>(fc2_w, c1w, c1b, c2w, c2b);
    kernelB<<<NSAMP / BM, 256, SMEM_TOTAL>>>(x0, fc1_w, fc1_b, ln1_g, ln1_b,
                                             fc2_b, ln2_g, ln2_b, out);
    select_persistent<<<NBLK, 256>>>(out);
}

// round 10
// speedup vs baseline: 2.1993x; 1.0454x over previous
#include <cuda_runtime.h>
#include <cuda_bf16.h>
#include <math.h>
#include <stdint.h>

// Problem constants
#define BATCH 8
#define SEQ   4096
#define PP    400           // 20x20
#define NSAMP (BATCH*SEQ)   // 32768
#define ITERS 12
#define NBLK  256           // persistent selection grid

// GEMM: M=32768 (64/CTA), N=448 (56 n8-tiles, 7 per warp), K=400 (25 k16-steps)
#define NK16  25
#define NNT   56

typedef unsigned long long u64;

// ---------------- scratch (static __device__, no allocations) ----------------
__device__ unsigned g_Bfrag[NK16 * NNT * 2 * 64];  // [k16][nt][plane][lane][2] u32
__device__ float  g_m[NSAMP];
__device__ float  g_keff[25];
__device__ float  g_c;
__device__ float  g_act[BATCH * PP];
__device__ int    g_sel[BATCH * PP];
__device__ int    g_done[BATCH];
__device__ float  g_res[BATCH * SEQ];
__device__ float  g_v2[BATCH * SEQ];
__device__ unsigned g_bar;

// ---------------- helpers ----------------
__device__ __forceinline__ void bsplit(float lo, float hi, uint32_t& h, uint32_t& l)
{
    asm("cvt.rn.bf16x2.f32 %0,%1,%2;" : "=r"(h) : "f"(hi), "f"(lo));
    float hlo = __uint_as_float(h << 16);
    float hhi = __uint_as_float(h & 0xffff0000u);
    asm("cvt.rn.bf16x2.f32 %0,%1,%2;" : "=r"(l) : "f"(hi - hhi), "f"(lo - hlo));
}
__device__ __forceinline__ void mma16816(float* c, const uint32_t* a,
                                         uint32_t b0, uint32_t b1)
{
    asm volatile(
        "mma.sync.aligned.m16n8k16.row.col.f32.bf16.bf16.f32 "
        "{%0,%1,%2,%3},{%4,%5,%6,%7},{%8,%9},{%0,%1,%2,%3};"
        : "+f"(c[0]), "+f"(c[1]), "+f"(c[2]), "+f"(c[3])
        : "r"(a[0]), "r"(a[1]), "r"(a[2]), "r"(a[3]), "r"(b0), "r"(b1));
}

// ---------------- prep: B fragment planes + conv compose + barrier reset -----
__global__ void prep_kernel(const float* __restrict__ fc2_w,
                            const float* __restrict__ c1w, const float* __restrict__ c1b,
                            const float* __restrict__ c2w, const float* __restrict__ c2b)
{
    if (blockIdx.x < 700) {
        int e = blockIdx.x * 256 + threadIdx.x;   // [k16][nt][plane][lane][reg]
        int reg   = e & 1;
        int lane  = (e >> 1) & 31;
        int plane = (e >> 6) & 1;
        int r     = e >> 7;                        // 0..1399
        int nt  = r % NNT;
        int k16 = r / NNT;
        int g = lane >> 2, tg = lane & 3;
        int n  = nt * 8 + g;
        int kr = k16 * 16 + tg * 2 + reg * 8;
        float v0 = (n < PP) ? fc2_w[n * PP + kr] : 0.f;
        float v1 = (n < PP) ? fc2_w[n * PP + kr + 1] : 0.f;
        uint32_t h, l;
        bsplit(v0, v1, h, l);                      // lo half = k row kr, hi = kr+1
        g_Bfrag[(((size_t)r * 2 + plane) * 32 + lane) * 2 + reg] = plane ? l : h;
        return;
    }
    // last block: keff compose + g_bar reset
    __shared__ float s1w[45], s1b[5], s2w[450], s2b[10], part[250];
    int t = threadIdx.x;
    if (t == 0) g_bar = 0u;
    if (t < 45)  s1w[t] = c1w[t];
    if (t < 5)   s1b[t] = c1b[t];
    for (int i = t; i < 450; i += 256) s2w[i] = c2w[i];
    if (t < 10)  s2b[t] = c2b[t];
    __syncthreads();
    if (t < 250) {
        int uv = t / 10, oc = t % 10;
        int u = uv / 5, v = uv % 5;
        float acc = 0.f;
        for (int ic = 0; ic < 5; ++ic)
#pragma unroll
            for (int ay = 0; ay < 3; ++ay) {
                int by = u - ay; if (by < 0 || by > 2) continue;
#pragma unroll
                for (int ax = 0; ax < 3; ++ax) {
                    int bx = v - ax; if (bx < 0 || bx > 2) continue;
                    acc += s2w[((oc * 5 + ic) * 3 + by) * 3 + bx] * s1w[(ic * 3 + ay) * 3 + ax];
                }
            }
        part[t] = acc;
    }
    __syncthreads();
    if (t < 25) {
        float acc = 0.f;
#pragma unroll
        for (int oc = 0; oc < 10; ++oc) acc += part[t * 10 + oc];
        g_keff[t] = acc * 0.1f;
    } else if (t == 25) {
        float acc = 0.f;
        for (int oc = 0; oc < 10; ++oc) {
            float t2 = s2b[oc];
            for (int ic = 0; ic < 5; ++ic) {
                float sw = 0.f;
#pragma unroll
                for (int bb = 0; bb < 9; ++bb) sw += s2w[(oc * 5 + ic) * 9 + bb];
                t2 += s1b[ic] * sw;
            }
            acc += t2;
        }
        g_c = acc * 0.1f;
    }
}

// ---- kernel B: fc1+ln1 + mma.sync bf16-split GEMM + ln2 + conv + 0.1*sigmoid
#define BM 64
#define AH_STRIDE 404
#define REGION (BM * AH_STRIDE)        // fp32 h1 tile, later reused as Cs
// float-index param offsets
#define P_FW   (REGION)                // 1200
#define P_FB   (P_FW + 1200)
#define P_L1G  (P_FB + PP)
#define P_L1B  (P_L1G + PP)
#define P_PB   (P_L1B + PP)
#define P_PG   (P_PB + PP)
#define P_PB2  (P_PG + PP)
#define P_KS   (P_PB2 + PP)            // 26
#define SMEM_TOTAL ((P_KS + 32) * 4)

__global__ void __launch_bounds__(256, 1) kernelB(
    const float* __restrict__ x0,
    const float* __restrict__ fc1_w, const float* __restrict__ fc1_b,
    const float* __restrict__ ln1_g, const float* __restrict__ ln1_b,
    const float* __restrict__ fc2_b, const float* __restrict__ ln2_g,
    const float* __restrict__ ln2_b, float* __restrict__ out)
{
    extern __shared__ float smf[];
    float* Ah = smf;                   // [64][404], fp32; overlaid by Cs later

    int tid = threadIdx.x, lane = tid & 31, wid = tid >> 5;
    int s0 = blockIdx.x * BM;

    for (int i = tid; i < 1200; i += 256) smf[P_FW + i] = fc1_w[i];
    for (int i = tid; i < PP; i += 256) {
        smf[P_FB + i] = fc1_b[i]; smf[P_L1G + i] = ln1_g[i]; smf[P_L1B + i] = ln1_b[i];
        smf[P_PB + i] = fc2_b[i]; smf[P_PG + i] = ln2_g[i]; smf[P_PB2 + i] = ln2_b[i];
    }
    if (tid < 26) smf[P_KS + tid] = (tid < 25) ? g_keff[tid] : g_c;
    __syncthreads();

    // ---- fused fc1 + relu + ln1 into Ah (one warp per sample, 8 rounds) ----
    for (int r = wid; r < BM; r += 8) {
        int ss = s0 + r;
        const float* xp = x0 + (size_t)ss * 3;
        float xa = xp[0], xb = xp[1], xc = xp[2];
        if (lane == 0) g_m[ss] = (xa + xb + xc) * (1.f / 3.f);
        float v[13];
        float sum = 0.f, sq = 0.f;
#pragma unroll
        for (int k = 0; k < 13; ++k) {
            int q = lane + 32 * k;
            float h = 0.f;
            if (q < PP) {
                h = fmaxf(xa * smf[P_FW + q * 3] + xb * smf[P_FW + q * 3 + 1]
                        + xc * smf[P_FW + q * 3 + 2] + smf[P_FB + q], 0.f);
            }
            v[k] = h; sum += h; sq += h * h;
        }
        for (int o = 16; o; o >>= 1) {
            sum += __shfl_xor_sync(~0u, sum, o);
            sq  += __shfl_xor_sync(~0u, sq, o);
        }
        float mu = sum * (1.f / PP);
        float var = sq * (1.f / PP) - mu * mu;
        float rs = rsqrtf(var + 1e-5f);
#pragma unroll
        for (int k = 0; k < 13; ++k) {
            int q = lane + 32 * k;
            if (q < PP) Ah[r * AH_STRIDE + q] = (v[k] - mu) * rs * smf[P_L1G + q] + smf[P_L1B + q];
        }
    }
    __syncthreads();

    // ---- mma.sync bf16-split mainloop ----
    // Each warp: ALL 4 m16-blocks x 7 n8-tiles (nt = wid*7+j). No B redundancy.
    int g = lane >> 2, tg = lane & 3;
    float acc[4][7][4];
#pragma unroll
    for (int mb = 0; mb < 4; ++mb)
#pragma unroll
        for (int j = 0; j < 7; ++j)
#pragma unroll
            for (int i = 0; i < 4; ++i) acc[mb][j][i] = 0.f;

    const u64* bfr = (const u64*)g_Bfrag;

    for (int k16 = 0; k16 < NK16; ++k16) {
        int kb = k16 * 16;
        uint32_t aH[4][4], aL[4][4];
#pragma unroll
        for (int mb = 0; mb < 4; ++mb) {
            const float* b0p = Ah + (16 * mb + g) * AH_STRIDE + 2 * tg + kb;
            const float* b1p = Ah + (16 * mb + 8 + g) * AH_STRIDE + 2 * tg + kb;
            float2 x0v = *(const float2*)b0p;
            float2 x1v = *(const float2*)b1p;
            float2 x2v = *(const float2*)(b0p + 8);
            float2 x3v = *(const float2*)(b1p + 8);
            bsplit(x0v.x, x0v.y, aH[mb][0], aL[mb][0]);
            bsplit(x1v.x, x1v.y, aH[mb][1], aL[mb][1]);
            bsplit(x2v.x, x2v.y, aH[mb][2], aL[mb][2]);
            bsplit(x3v.x, x3v.y, aH[mb][3], aL[mb][3]);
        }

        // u64 layout: index = r*64 + plane*32 + lane, where r = k16*NNT + nt
        size_t base = ((size_t)(k16 * NNT + wid * 7)) * 64 + lane;
#pragma unroll
        for (int j = 0; j < 7; ++j) {
            u64 w0 = bfr[base + (size_t)j * 64];        // plane 0 (hi)
            u64 w1 = bfr[base + (size_t)j * 64 + 32];   // plane 1 (residual)
            uint32_t bH0 = (uint32_t)w0, bH1 = (uint32_t)(w0 >> 32);
            uint32_t bL0 = (uint32_t)w1, bL1 = (uint32_t)(w1 >> 32);
#pragma unroll
            for (int mb = 0; mb < 4; ++mb) {
                mma16816(acc[mb][j], aH[mb], bH0, bH1);
                mma16816(acc[mb][j], aH[mb], bL0, bL1);
                mma16816(acc[mb][j], aL[mb], bH0, bH1);
            }
        }
    }
    __syncthreads();   // all mainloop reads of Ah done -> safe to overlay Cs

    // ---- bias + relu -> Cs (overlay Ah) ----
    float* Cs = Ah;
#pragma unroll
    for (int mb = 0; mb < 4; ++mb) {
        int rowa = (16 * mb + g) * AH_STRIDE;
        int rowb = (16 * mb + 8 + g) * AH_STRIDE;
#pragma unroll
        for (int j = 0; j < 7; ++j) {
            int q0 = (wid * 7 + j) * 8 + 2 * tg;
            if (q0 < PP) {
                Cs[rowa + q0] = fmaxf(acc[mb][j][0] + smf[P_PB + q0], 0.f);
                Cs[rowb + q0] = fmaxf(acc[mb][j][2] + smf[P_PB + q0], 0.f);
            }
            if (q0 + 1 < PP) {
                Cs[rowa + q0 + 1] = fmaxf(acc[mb][j][1] + smf[P_PB + q0 + 1], 0.f);
                Cs[rowb + q0 + 1] = fmaxf(acc[mb][j][3] + smf[P_PB + q0 + 1], 0.f);
            }
        }
    }
    __syncthreads();

    // ---- LN2 per sample row (8 warps x 8 rows) ----
    for (int r = wid * 8; r < wid * 8 + 8; ++r) {
        float sum = 0.f, sq = 0.f;
#pragma unroll
        for (int k = 0; k < 13; ++k) {
            int q = lane + 32 * k;
            if (q < PP) { float x = Cs[r * AH_STRIDE + q]; sum += x; sq += x * x; }
        }
        for (int o = 16; o; o >>= 1) {
            sum += __shfl_xor_sync(~0u, sum, o);
            sq  += __shfl_xor_sync(~0u, sq, o);
        }
        float mu = sum * (1.f / PP);
        float var = sq * (1.f / PP) - mu * mu;
        float rs = rsqrtf(var + 1e-5f);
#pragma unroll
        for (int k = 0; k < 13; ++k) {
            int q = lane + 32 * k;
            if (q < PP) {
                float x = Cs[r * AH_STRIDE + q];
                Cs[r * AH_STRIDE + q] = (x - mu) * rs * smf[P_PG + q] + smf[P_PB2 + q];
            }
        }
    }
    __syncthreads();

    // ---- 5x5 circular conv + 0.1*sigmoid + transposed write ----
    int b = s0 >> 12;
    int sw0 = s0 & (SEQ - 1);
    float kreg[25];
#pragma unroll
    for (int d = 0; d < 25; ++d) kreg[d] = smf[P_KS + d];
    float cc0 = smf[P_KS + 25];

    for (int item = tid; item < 800; item += 256) {
        int r8 = (item & 7) * 8;
        int pgi = item >> 3;
        int ii = pgi / 5, jj0 = (pgi % 5) * 4;
        int wy[5], wx[8];
#pragma unroll
        for (int dy = 0; dy < 5; ++dy) wy[dy] = ((ii + dy - 2 + 20) % 20) * 20;
#pragma unroll
        for (int dx = 0; dx < 8; ++dx) wx[dx] = (jj0 + dx - 2 + 20) % 20;

        float o[4][8];
#pragma unroll
        for (int rr = 0; rr < 8; ++rr) {
            const float* crow = Cs + (r8 + rr) * AH_STRIDE;
            float patch[5][8];
#pragma unroll
            for (int dy = 0; dy < 5; ++dy)
#pragma unroll
                for (int dx = 0; dx < 8; ++dx)
                    patch[dy][dx] = crow[wy[dy] + wx[dx]];
#pragma unroll
            for (int t = 0; t < 4; ++t) {
                float a = cc0;
#pragma unroll
                for (int du = 0; du < 5; ++du)
#pragma unroll
                    for (int dv = 0; dv < 5; ++dv)
                        a += kreg[du * 5 + dv] * patch[du][t + dv];
                o[t][rr] = 0.1f / (1.f + __expf(-a));
            }
        }
#pragma unroll
        for (int t = 0; t < 4; ++t) {
            int p = ii * 20 + jj0 + t;
            float* obase = out + ((size_t)(b * PP + p)) * SEQ + sw0 + r8;
            *(float4*)(obase)     = make_float4(o[t][0], o[t][1], o[t][2], o[t][3]);
            *(float4*)(obase + 4) = make_float4(o[t][4], o[t][5], o[t][6], o[t][7]);
        }
    }
}

// ---------------- persistent selection (unchanged, proven) ------------------
__device__ __forceinline__ void gbar(unsigned& target)
{
    __syncthreads();
    __threadfence();
    if (threadIdx.x == 0) {
        atomicAdd(&g_bar, 1u);
        while (*(volatile unsigned*)&g_bar < target) { }
    }
    __syncthreads();
    __threadfence();
}

__global__ void __launch_bounds__(256) select_persistent(float* __restrict__ out)
{
    int b = blockIdx.x & 7;
    int g = blockIdx.x >> 3;
    int tid = threadIdx.x, lane = tid & 31, wid = tid >> 5;
    unsigned target = 0;
    __shared__ float ws[8];
    __shared__ float wvv[8];
    __shared__ int   wii[8];
    __shared__ float rsum[8];
    __shared__ int   s_pid, s_brk;

    if (g < 16) {
        int s = g * 256 + tid;
        float m = g_m[b * SEQ + s];
        g_res[b * SEQ + s] = 1.f;
        g_v2[b * SEQ + s] = m * m;
    } else if (g == 16 || g == 17) {
        int p = (g - 16) * 256 + tid;
        if (p < PP) g_sel[b * PP + p] = 0;
    } else if (g == 18 && tid == 0) {
        g_done[b] = 0;
    }
    target += NBLK; gbar(target);

    for (int it = 0; it < ITERS; ++it) {
        if (!g_done[b]) {
            const float4* vv = (const float4*)(g_v2 + (size_t)b * SEQ);
            for (int p = g; p < PP; p += 32) {
                if (g_sel[b * PP + p]) {
                    if (tid == 0) g_act[b * PP + p] = -1.f;
                    continue;
                }
                const float4* wp = (const float4*)(out + ((size_t)(b * PP + p)) * SEQ);
                float a = 0.f;
#pragma unroll
                for (int j = 0; j < 4; ++j) {
                    int k = tid + 256 * j;
                    float4 x = wp[k]; float4 y = vv[k];
                    a += x.x * x.x * y.x + x.y * x.y * y.y
                       + x.z * x.z * y.z + x.w * x.w * y.w;
                }
                for (int o = 16; o; o >>= 1) a += __shfl_xor_sync(~0u, a, o);
                if (lane == 0) ws[wid] = a;
                __syncthreads();
                if (tid == 0) {
                    float t = 0.f;
#pragma unroll
                    for (int i = 0; i < 8; ++i) t += ws[i];
                    g_act[b * PP + p] = t;
                }
                __syncthreads();
            }
        }
        target += NBLK; gbar(target);

        if (g == 0 && !g_done[b]) {
            float bv = -2.f; int bi = 0x7fffffff;
            for (int p = tid; p < PP; p += 256) {
                float v = g_act[b * PP + p];
                if (v > bv || (v == bv && p < bi)) { bv = v; bi = p; }
            }
            for (int o = 16; o; o >>= 1) {
                float ov = __shfl_xor_sync(~0u, bv, o);
                int   oi = __shfl_xor_sync(~0u, bi, o);
                if (ov > bv || (ov == bv && oi < bi)) { bv = ov; bi = oi; }
            }
            if (lane == 0) { wvv[wid] = bv; wii[wid] = bi; }
            __syncthreads();
            if (tid == 0) {
                float fv = -2.f; int fi = 0x7fffffff;
#pragma unroll
                for (int i = 0; i < 8; ++i)
                    if (wvv[i] > fv || (wvv[i] == fv && wii[i] < fi)) { fv = wvv[i]; fi = wii[i]; }
                s_pid = fi; g_sel[b * PP + fi] = 1;
            }
            __syncthreads();
            int pid = s_pid;

            const float* row = out + ((size_t)(b * PP + pid)) * SEQ;
            float loc = 0.f;
            for (int s = tid; s < SEQ; s += 256) {
                float r = g_res[b * SEQ + s] - row[s] * 10.f;
                r = fmaxf(r, 0.f);
                g_res[b * SEQ + s] = r;
                loc += r;
                float v = r * g_m[b * SEQ + s];
                g_v2[b * SEQ + s] = v * v;
            }
            for (int o = 16; o; o >>= 1) loc += __shfl_xor_sync(~0u, loc, o);
            if (lane == 0) rsum[wid] = loc;
            __syncthreads();
            if (tid == 0) {
                float t = 0.f;
#pragma unroll
                for (int i = 0; i < 8; ++i) t += rsum[i];
                if (t * (1.f / SEQ) < 0.05f) g_done[b] = 1;
            }
        }
        target += NBLK; gbar(target);

        if (tid == 0) {
            int ad = 1;
#pragma unroll
            for (int i = 0; i < 8; ++i) ad &= g_done[i];
            s_brk = ad;
        }
        __syncthreads();
        if (s_brk) break;
        __syncthreads();
    }

    for (int p = g; p < PP; p += 32) {
        if (g_sel[b * PP + p]) {
            float4* wp = (float4*)(out + ((size_t)(b * PP + p)) * SEQ);
#pragma unroll
            for (int j = 0; j < 4; ++j) {
                int k = tid + 256 * j;
                float4 x = wp[k];
                x.x *= 10.f; x.y *= 10.f; x.z *= 10.f; x.w *= 10.f;
                wp[k] = x;
            }
        }
    }
}

// ---------------- launch --------------------------------------------------
extern "C" void kernel_launch(void* const* d_in, const int* in_sizes, int n_in,
                              void* d_out, int out_size)
{
    const float* x0     = (const float*)d_in[0];
    const float* fc1_w  = (const float*)d_in[1];
    const float* fc1_b  = (const float*)d_in[2];
    const float* ln1_g  = (const float*)d_in[3];
    const float* ln1_b  = (const float*)d_in[4];
    const float* fc2_w  = (const float*)d_in[5];
    const float* fc2_b  = (const float*)d_in[6];
    const float* ln2_g  = (const float*)d_in[7];
    const float* ln2_b  = (const float*)d_in[8];
    const float* c1w    = (const float*)d_in[9];
    const float* c1b    = (const float*)d_in[10];
    const float* c2w    = (const float*)d_in[11];
    const float* c2b    = (const float*)d_in[12];
    float* out = (float*)d_out;

    cudaFuncSetAttribute(kernelB, cudaFuncAttributeMaxDynamicSharedMemorySize, SMEM_TOTAL);

    prep_kernel<<<701, 256>>>(fc2_w, c1w, c1b, c2w, c2b);
    kernelB<<<NSAMP / BM, 256, SMEM_TOTAL>>>(x0, fc1_w, fc1_b, ln1_g, ln1_b,
                                             fc2_b, ln2_g, ln2_b, out);
    select_persistent<<<NBLK, 256>>>(out);
}